// round 2
// baseline (speedup 1.0000x reference)
#include <cuda_runtime.h>
#include <cuda_bf16.h>
#include <math.h>

#define DIMM   1024
#define HEADS  16
#define HD     64
#define CC     128
#define BSZ    4
#define TLEN   4096
#define NCH    (TLEN/CC)        /* 32 */
#define MTOT   (BSZ*TLEN)       /* 16384 */

#define YN  (MTOT*DIMM)         /* 16777216 */
#define SN  (BSZ*HEADS*HD*HD)   /* 262144   */

// ---------------- scratch (module-load allocated, no cudaMalloc) ----------------
__device__ float g_q [MTOT*DIMM];
__device__ float g_k [MTOT*DIMM];
__device__ float g_v [MTOT*DIMM];
__device__ float g_bt[MTOT*DIMM];   // softplus(beta_logits)
__device__ float g_la[MTOT*DIMM];   // log_sigmoid(alpha_logits)
__device__ float g_m [BSZ*NCH*HEADS*CC];   // cumsum of mean log_alpha within chunk
__device__ float g_bm[BSZ*NCH*HEADS*CC];   // mean beta over head dim

__device__ __forceinline__ float softplusf(float x) {
    return fmaxf(x, 0.0f) + log1pf(expf(-fabsf(x)));
}

// ---------------- kernel 1: fused 5-way projection SGEMM ----------------
// C[m, n] = sum_k x[m,k] * W[n,k]  (both K-contiguous, "NT" gemm)
// BM=BN=128, BK=8, 256 threads, 8x8 microtile, transposed smem tiles.
__global__ __launch_bounds__(256) void proj_kernel(
    const float* __restrict__ x,
    const float* __restrict__ Wq, const float* __restrict__ bq,
    const float* __restrict__ Wk, const float* __restrict__ bk,
    const float* __restrict__ Wv, const float* __restrict__ bv,
    const float* __restrict__ Wb, const float* __restrict__ bb,
    const float* __restrict__ Wa, const float* __restrict__ ba,
    float* __restrict__ alpha_out)
{
    __shared__ float As[8][132];
    __shared__ float Bs[8][132];
    const int tid = threadIdx.x;
    const int nb  = blockIdx.x;        // 0..39  (5120 output cols / 128)
    const int mb  = blockIdx.y;        // 0..127
    const int wi  = nb >> 3;           // which weight matrix (1024/128 = 8 tiles each)
    const float* W; const float* bias;
    if      (wi == 0) { W = Wq; bias = bq; }
    else if (wi == 1) { W = Wk; bias = bk; }
    else if (wi == 2) { W = Wv; bias = bv; }
    else if (wi == 3) { W = Wb; bias = bb; }
    else              { W = Wa; bias = ba; }
    const int m0 = mb * 128;
    const int r0 = (nb & 7) * 128;     // row offset inside this weight matrix
    const int lr = tid >> 1;           // 0..127
    const int lc = (tid & 1) << 2;     // 0 or 4
    const float* Ap = x + (m0 + lr) * DIMM + lc;
    const float* Bp = W + (r0 + lr) * DIMM + lc;
    const int tx = tid & 15;
    const int ty = tid >> 4;

    float acc[8][8];
    #pragma unroll
    for (int i = 0; i < 8; i++) {
        #pragma unroll
        for (int j = 0; j < 8; j++) acc[i][j] = 0.0f;
    }

    for (int k0 = 0; k0 < DIMM; k0 += 8) {
        float4 a4 = *(const float4*)(Ap + k0);
        float4 b4 = *(const float4*)(Bp + k0);
        As[lc+0][lr] = a4.x; As[lc+1][lr] = a4.y; As[lc+2][lr] = a4.z; As[lc+3][lr] = a4.w;
        Bs[lc+0][lr] = b4.x; Bs[lc+1][lr] = b4.y; Bs[lc+2][lr] = b4.z; Bs[lc+3][lr] = b4.w;
        __syncthreads();
        #pragma unroll
        for (int kk = 0; kk < 8; kk++) {
            float ar[8], br[8];
            *(float4*)&ar[0] = *(const float4*)&As[kk][ty*8];
            *(float4*)&ar[4] = *(const float4*)&As[kk][ty*8+4];
            *(float4*)&br[0] = *(const float4*)&Bs[kk][tx*8];
            *(float4*)&br[4] = *(const float4*)&Bs[kk][tx*8+4];
            #pragma unroll
            for (int i = 0; i < 8; i++) {
                #pragma unroll
                for (int j = 0; j < 8; j++)
                    acc[i][j] = fmaf(ar[i], br[j], acc[i][j]);
            }
        }
        __syncthreads();
    }

    float bl[8];
    #pragma unroll
    for (int j = 0; j < 8; j++) bl[j] = bias[r0 + tx*8 + j];

    #pragma unroll
    for (int i = 0; i < 8; i++) {
        const int t   = m0 + ty*8 + i;
        const int off = t * DIMM + r0 + tx*8;
        float v[8];
        #pragma unroll
        for (int j = 0; j < 8; j++) v[j] = acc[i][j] + bl[j];
        if (wi <= 1) {
            #pragma unroll
            for (int j = 0; j < 8; j++) v[j] *= 0.125f;      // d^-0.5
            float* g = (wi == 0) ? g_q : g_k;
            *(float4*)(g + off)     = make_float4(v[0],v[1],v[2],v[3]);
            *(float4*)(g + off + 4) = make_float4(v[4],v[5],v[6],v[7]);
        } else if (wi == 2) {
            *(float4*)(g_v + off)     = make_float4(v[0],v[1],v[2],v[3]);
            *(float4*)(g_v + off + 4) = make_float4(v[4],v[5],v[6],v[7]);
        } else if (wi == 3) {
            #pragma unroll
            for (int j = 0; j < 8; j++) v[j] = softplusf(v[j]);
            *(float4*)(g_bt + off)     = make_float4(v[0],v[1],v[2],v[3]);
            *(float4*)(g_bt + off + 4) = make_float4(v[4],v[5],v[6],v[7]);
        } else {
            float sg[8], la[8];
            #pragma unroll
            for (int j = 0; j < 8; j++) {
                float z = fminf(10.0f, fmaxf(-10.0f, v[j]));
                sg[j] = 1.0f / (1.0f + expf(-z));
                la[j] = -softplusf(-z);              // log_sigmoid(z)
            }
            *(float4*)(alpha_out + off)     = make_float4(sg[0],sg[1],sg[2],sg[3]);
            *(float4*)(alpha_out + off + 4) = make_float4(sg[4],sg[5],sg[6],sg[7]);
            *(float4*)(g_la + off)     = make_float4(la[0],la[1],la[2],la[3]);
            *(float4*)(g_la + off + 4) = make_float4(la[4],la[5],la[6],la[7]);
        }
    }
}

// ---------------- kernel 2: per-chunk stats ----------------
// block = (b, n, h); thread = c. m[c] = cumsum_c(mean_d log_alpha), bmean[c] = mean_d beta
__global__ __launch_bounds__(128) void stats_kernel()
{
    const int bid = blockIdx.x;
    const int c = threadIdx.x;
    const int h = bid & 15;
    const int n = (bid >> 4) & 31;
    const int b = bid >> 9;
    const int t = b * TLEN + n * CC + c;
    const int base = t * DIMM + h * HD;
    float sla = 0.0f, sb = 0.0f;
    #pragma unroll
    for (int d4 = 0; d4 < HD; d4 += 4) {
        float4 u = *(const float4*)(g_la + base + d4);
        float4 w = *(const float4*)(g_bt + base + d4);
        sla += u.x + u.y + u.z + u.w;
        sb  += w.x + w.y + w.z + w.w;
    }
    g_bm[bid * CC + c] = sb * (1.0f/64.0f);
    __shared__ float smem[CC];
    smem[c] = sla * (1.0f/64.0f);
    __syncthreads();
    #pragma unroll
    for (int off = 1; off < CC; off <<= 1) {
        float prev = (c >= off) ? smem[c - off] : 0.0f;
        __syncthreads();
        smem[c] += prev;
        __syncthreads();
    }
    g_m[bid * CC + c] = smem[c];
}

// ---------------- kernel 3: intra-chunk attention ----------------
// block = (b, n, h). S = (q k^T) * exp(m_i - m_j) on lower-tri, Y = S @ (v*beta)
#define S3_QST 0
#define S3_KST (64*132)
#define S3_VBS (2*64*132)
#define S3_MS  (2*64*132 + 128*68)
#define S3_SS  (S3_MS + 128)
#define S3_FLOATS (S3_SS + 128*132)
#define S3_BYTES (S3_FLOATS * 4)

__global__ __launch_bounds__(256) void intra_kernel(float* __restrict__ y_out)
{
    extern __shared__ float sm[];
    float* qst = sm + S3_QST;   // [64 kk][132] transposed
    float* kst = sm + S3_KST;   // [64 kk][132] transposed
    float* vbs = sm + S3_VBS;   // [128 c][68] row-major, holds v*beta
    float* ms  = sm + S3_MS;    // [128]
    float* Ss  = sm + S3_SS;    // [128 i][132]
    const int tid = threadIdx.x;
    const int bid = blockIdx.x;
    const int h = bid & 15;
    const int n = (bid >> 4) & 31;
    const int b = bid >> 9;
    const int tbase = b * TLEN + n * CC;

    #pragma unroll
    for (int it = 0; it < 8; it++) {
        int f  = tid + it * 256;          // 0..2047
        int c  = f >> 4;
        int d4 = (f & 15) << 2;
        int g  = (tbase + c) * DIMM + h * HD + d4;
        float4 q4 = *(const float4*)(g_q  + g);
        float4 k4 = *(const float4*)(g_k  + g);
        float4 v4 = *(const float4*)(g_v  + g);
        float4 b4 = *(const float4*)(g_bt + g);
        qst[(d4+0)*132 + c] = q4.x; qst[(d4+1)*132 + c] = q4.y;
        qst[(d4+2)*132 + c] = q4.z; qst[(d4+3)*132 + c] = q4.w;
        kst[(d4+0)*132 + c] = k4.x; kst[(d4+1)*132 + c] = k4.y;
        kst[(d4+2)*132 + c] = k4.z; kst[(d4+3)*132 + c] = k4.w;
        *(float4*)(vbs + c*68 + d4) =
            make_float4(v4.x*b4.x, v4.y*b4.y, v4.z*b4.z, v4.w*b4.w);
    }
    if (tid < 128) ms[tid] = g_m[bid * CC + tid];
    __syncthreads();

    // phase B: S = q k^T (8x8 microtile per thread)
    const int tx = tid & 15, ty = tid >> 4;
    float acc[8][8];
    #pragma unroll
    for (int i = 0; i < 8; i++) {
        #pragma unroll
        for (int j = 0; j < 8; j++) acc[i][j] = 0.0f;
    }
    #pragma unroll 8
    for (int kk = 0; kk < 64; kk++) {
        float a[8], bb2[8];
        *(float4*)&a[0]   = *(const float4*)&qst[kk*132 + ty*8];
        *(float4*)&a[4]   = *(const float4*)&qst[kk*132 + ty*8 + 4];
        *(float4*)&bb2[0] = *(const float4*)&kst[kk*132 + tx*8];
        *(float4*)&bb2[4] = *(const float4*)&kst[kk*132 + tx*8 + 4];
        #pragma unroll
        for (int i = 0; i < 8; i++) {
            #pragma unroll
            for (int j = 0; j < 8; j++)
                acc[i][j] = fmaf(a[i], bb2[j], acc[i][j]);
        }
    }
    float mi[8], mj[8];
    #pragma unroll
    for (int i = 0; i < 8; i++) mi[i] = ms[ty*8 + i];
    #pragma unroll
    for (int j = 0; j < 8; j++) mj[j] = ms[tx*8 + j];
    #pragma unroll
    for (int i = 0; i < 8; i++) {
        const int gi = ty*8 + i;
        float sv[8];
        #pragma unroll
        for (int j = 0; j < 8; j++) {
            const int gj = tx*8 + j;
            sv[j] = (gj <= gi) ? acc[i][j] * expf(mi[i] - mj[j]) : 0.0f;
        }
        *(float4*)&Ss[gi*132 + tx*8]     = make_float4(sv[0],sv[1],sv[2],sv[3]);
        *(float4*)&Ss[gi*132 + tx*8 + 4] = make_float4(sv[4],sv[5],sv[6],sv[7]);
    }
    __syncthreads();

    // phase C: Y = S @ vb ; thread -> 4 rows x 8 cols
    const int tx2 = tid & 7, ty2 = tid >> 3;
    const int i0 = ty2 * 4, dd0 = tx2 * 8;
    float y0[8], y1[8], y2[8], y3[8];
    #pragma unroll
    for (int e = 0; e < 8; e++) { y0[e]=0.f; y1[e]=0.f; y2[e]=0.f; y3[e]=0.f; }
    #pragma unroll 4
    for (int j = 0; j < CC; j++) {
        float s0 = Ss[(i0+0)*132 + j];
        float s1 = Ss[(i0+1)*132 + j];
        float s2 = Ss[(i0+2)*132 + j];
        float s3 = Ss[(i0+3)*132 + j];
        float vv[8];
        *(float4*)&vv[0] = *(const float4*)&vbs[j*68 + dd0];
        *(float4*)&vv[4] = *(const float4*)&vbs[j*68 + dd0 + 4];
        #pragma unroll
        for (int e = 0; e < 8; e++) {
            y0[e] = fmaf(s0, vv[e], y0[e]);
            y1[e] = fmaf(s1, vv[e], y1[e]);
            y2[e] = fmaf(s2, vv[e], y2[e]);
            y3[e] = fmaf(s3, vv[e], y3[e]);
        }
    }
    {
        int off = (tbase + i0 + 0) * DIMM + h * HD + dd0;
        *(float4*)(y_out + off)     = make_float4(y0[0],y0[1],y0[2],y0[3]);
        *(float4*)(y_out + off + 4) = make_float4(y0[4],y0[5],y0[6],y0[7]);
        off += DIMM;
        *(float4*)(y_out + off)     = make_float4(y1[0],y1[1],y1[2],y1[3]);
        *(float4*)(y_out + off + 4) = make_float4(y1[4],y1[5],y1[6],y1[7]);
        off += DIMM;
        *(float4*)(y_out + off)     = make_float4(y2[0],y2[1],y2[2],y2[3]);
        *(float4*)(y_out + off + 4) = make_float4(y2[4],y2[5],y2[6],y2[7]);
        off += DIMM;
        *(float4*)(y_out + off)     = make_float4(y3[0],y3[1],y3[2],y3[3]);
        *(float4*)(y_out + off + 4) = make_float4(y3[4],y3[5],y3[6],y3[7]);
    }
}

// ---------------- kernel 4: inter-chunk scan (serial over N, parallel over v-dim) ----------------
// block = (b, h, slice of 8 v-cols); state [64 kk][8 dd] lives in smem.
__global__ __launch_bounds__(128) void scan_kernel(float* __restrict__ y_out,
                                                   float* __restrict__ state_out)
{
    __shared__ float buf[128*68];   // q transposed [64][132] OR k row-major [128][68]
    __shared__ float vB[128*8];     // v * bmean, this slice
    __shared__ float curve[128];
    __shared__ float st[64*8];
    const int slice = blockIdx.x;       // 0..7
    const int bh = blockIdx.y;          // 0..63
    const int b = bh >> 4, h = bh & 15;
    const int dd0 = slice * 8;
    const int tid = threadIdx.x;
    const int dd = tid & 7;

    for (int i = tid; i < 64*8; i += 128) st[i] = 0.0f;
    __syncthreads();

    for (int n = 0; n < NCH; n++) {
        const int tb = b * TLEN + n * CC;
        const int mbase = ((b * NCH + n) * HEADS + h) * CC;

        // phase 1: q transposed + curve
        #pragma unroll
        for (int it = 0; it < 16; it++) {
            int f = tid + it * 128;          // 0..2047
            int c = f >> 4;
            int d4 = (f & 15) << 2;
            float4 q4 = *(const float4*)(g_q + (tb + c)*DIMM + h*HD + d4);
            buf[(d4+0)*132 + c] = q4.x; buf[(d4+1)*132 + c] = q4.y;
            buf[(d4+2)*132 + c] = q4.z; buf[(d4+3)*132 + c] = q4.w;
        }
        curve[tid] = expf(g_m[mbase + tid]);
        __syncthreads();

        // phase 2: mem = q @ state ; y += mem * curve
        {
            const int cg = tid >> 3;        // 0..15 -> rows cg*8..cg*8+7
            float a[8];
            #pragma unroll
            for (int cc = 0; cc < 8; cc++) a[cc] = 0.0f;
            #pragma unroll 16
            for (int kk = 0; kk < 64; kk++) {
                float s = st[kk*8 + dd];
                float q0[4], q1[4];
                *(float4*)q0 = *(const float4*)&buf[kk*132 + cg*8];
                *(float4*)q1 = *(const float4*)&buf[kk*132 + cg*8 + 4];
                a[0] = fmaf(q0[0], s, a[0]); a[1] = fmaf(q0[1], s, a[1]);
                a[2] = fmaf(q0[2], s, a[2]); a[3] = fmaf(q0[3], s, a[3]);
                a[4] = fmaf(q1[0], s, a[4]); a[5] = fmaf(q1[1], s, a[5]);
                a[6] = fmaf(q1[2], s, a[6]); a[7] = fmaf(q1[3], s, a[7]);
            }
            #pragma unroll
            for (int cc = 0; cc < 8; cc++) {
                int c = cg*8 + cc;
                int off = (tb + c)*DIMM + h*HD + dd0 + dd;
                y_out[off] += a[cc] * curve[c];
            }
        }
        __syncthreads();

        // phase 3: k row-major + v*bmean slice (reuse buf)
        #pragma unroll
        for (int it = 0; it < 16; it++) {
            int f = tid + it * 128;
            int c = f >> 4;
            int d4 = (f & 15) << 2;
            *(float4*)(buf + c*68 + d4) =
                *(const float4*)(g_k + (tb + c)*DIMM + h*HD + d4);
        }
        {
            int c = tid;
            float bm = g_bm[mbase + c];
            int g = (tb + c)*DIMM + h*HD + dd0;
            float4 v0 = *(const float4*)(g_v + g);
            float4 v1 = *(const float4*)(g_v + g + 4);
            vB[c*8+0]=v0.x*bm; vB[c*8+1]=v0.y*bm; vB[c*8+2]=v0.z*bm; vB[c*8+3]=v0.w*bm;
            vB[c*8+4]=v1.x*bm; vB[c*8+5]=v1.y*bm; vB[c*8+6]=v1.z*bm; vB[c*8+7]=v1.w*bm;
        }
        __syncthreads();

        // phase 4: state = state*asum + k^T @ (v*bmean)
        {
            const int kkg = tid >> 3;       // 0..15 -> kk = kkg*4 + r
            const float asum = curve[CC-1]; // exp(m[127]) = exp(sum log_alpha mean)
            float ns[4];
            #pragma unroll
            for (int r = 0; r < 4; r++) ns[r] = st[(kkg*4 + r)*8 + dd] * asum;
            #pragma unroll 8
            for (int c = 0; c < CC; c++) {
                float vb1 = vB[c*8 + dd];
                float4 k4 = *(const float4*)&buf[c*68 + kkg*4];
                ns[0] = fmaf(k4.x, vb1, ns[0]);
                ns[1] = fmaf(k4.y, vb1, ns[1]);
                ns[2] = fmaf(k4.z, vb1, ns[2]);
                ns[3] = fmaf(k4.w, vb1, ns[3]);
            }
            #pragma unroll
            for (int r = 0; r < 4; r++) st[(kkg*4 + r)*8 + dd] = ns[r];
        }
        __syncthreads();
    }

    // final state -> d_out[YN ..)
    {
        const int kkg = tid >> 3;
        #pragma unroll
        for (int r = 0; r < 4; r++) {
            int kk = kkg*4 + r;
            state_out[((b*HEADS + h)*HD + kk)*HD + dd0 + dd] = st[kk*8 + dd];
        }
    }
}

// ---------------- launch ----------------
extern "C" void kernel_launch(void* const* d_in, const int* in_sizes, int n_in,
                              void* d_out, int out_size)
{
    (void)in_sizes; (void)n_in; (void)out_size;
    const float* x  = (const float*)d_in[0];
    const float* Wq = (const float*)d_in[1];
    const float* bq = (const float*)d_in[2];
    const float* Wk = (const float*)d_in[3];
    const float* bk = (const float*)d_in[4];
    const float* Wv = (const float*)d_in[5];
    const float* bv = (const float*)d_in[6];
    const float* Wb = (const float*)d_in[7];
    const float* bb = (const float*)d_in[8];
    const float* Wa = (const float*)d_in[9];
    const float* ba = (const float*)d_in[10];

    float* out       = (float*)d_out;
    float* y_out     = out;              // [B,T,D]
    float* state_out = out + YN;         // [B,H,d,d]
    float* alpha_out = out + YN + SN;    // [B,T,H,d]

    cudaFuncSetAttribute(intra_kernel,
                         cudaFuncAttributeMaxDynamicSharedMemorySize, S3_BYTES);

    dim3 g1(40, 128);
    proj_kernel<<<g1, 256>>>(x, Wq, bq, Wk, bk, Wv, bv, Wb, bb, Wa, ba, alpha_out);
    stats_kernel<<<BSZ*NCH*HEADS, 128>>>();
    intra_kernel<<<BSZ*NCH*HEADS, 256, S3_BYTES>>>(y_out);
    dim3 g4(8, BSZ*HEADS);
    scan_kernel<<<g4, 128>>>(y_out, state_out);
}

// round 4
// speedup vs baseline: 1.7458x; 1.7458x over previous
#include <cuda_runtime.h>
#include <cuda_bf16.h>
#include <math.h>
#include <stdint.h>

#define DIMM   1024
#define HEADS  16
#define HD     64
#define CC     128
#define BSZ    4
#define TLEN   4096
#define NCH    (TLEN/CC)        /* 32 */
#define MTOT   (BSZ*TLEN)       /* 16384 */
#define K2     3072             /* split-bf16 K dim */
#define NOUT   5120             /* 5 matrices x 1024 */

#define YN  (MTOT*DIMM)
#define SN  (BSZ*HEADS*HD*HD)

// ---------------- scratch ----------------
__device__ float g_q [MTOT*DIMM];
__device__ float g_k [MTOT*DIMM];
__device__ float g_v [MTOT*DIMM];
__device__ float g_bt[MTOT*DIMM];
__device__ float g_la[MTOT*DIMM];
__device__ float g_m [BSZ*NCH*HEADS*CC];
__device__ float g_bm[BSZ*NCH*HEADS*CC];
__device__ __nv_bfloat16 g_x2[(size_t)MTOT*K2];   // [M,3072] = [hi|lo|hi]
__device__ __nv_bfloat16 g_w2[(size_t)NOUT*K2];   // [5120,3072] = [hi|hi|lo]
__device__ float g_delta[(size_t)BSZ*NCH*HEADS*HD*HD];
__device__ float g_stin [(size_t)BSZ*NCH*HEADS*HD*HD];

__device__ __forceinline__ float softplusf(float x) {
    return fmaxf(x, 0.0f) + log1pf(expf(-fabsf(x)));
}
__device__ __forceinline__ uint32_t s2u(const void* p) {
    uint32_t a;
    asm("{ .reg .u64 t; cvta.to.shared.u64 t, %1; cvt.u32.u64 %0, t; }"
        : "=r"(a) : "l"(p));
    return a;
}
#define CP16(dst,src) asm volatile("cp.async.cg.shared.global [%0], [%1], 16;" ::"r"(dst),"l"(src):"memory")
#define CP_COMMIT()   asm volatile("cp.async.commit_group;" :::"memory")
#define CP_WAIT1()    asm volatile("cp.async.wait_group 1;" :::"memory")

#define LDM_X4(r0,r1,r2,r3,addr) \
    asm volatile("ldmatrix.sync.aligned.m8n8.x4.shared.b16 {%0,%1,%2,%3}, [%4];" \
        : "=r"(r0),"=r"(r1),"=r"(r2),"=r"(r3) : "r"(addr))

#define MMA16816(d0,d1,d2,d3,a0,a1,a2,a3,b0,b1) \
    asm volatile("mma.sync.aligned.m16n8k16.row.col.f32.bf16.bf16.f32 " \
        "{%0,%1,%2,%3}, {%4,%5,%6,%7}, {%8,%9}, {%0,%1,%2,%3};" \
        : "+f"(d0),"+f"(d1),"+f"(d2),"+f"(d3) \
        : "r"(a0),"r"(a1),"r"(a2),"r"(a3),"r"(b0),"r"(b1))

// ---------------- conversion kernels ----------------
__global__ __launch_bounds__(256) void conv_x_kernel(const float* __restrict__ x)
{
    size_t i4 = (size_t)blockIdx.x * 256 + threadIdx.x;
    float4 v = ((const float4*)x)[i4];
    size_t m = i4 >> 8;
    int k4 = (int)(i4 & 255);
    __nv_bfloat16 h[4], l[4];
    float vv[4] = {v.x, v.y, v.z, v.w};
    #pragma unroll
    for (int e = 0; e < 4; e++) {
        h[e] = __float2bfloat16(vv[e]);
        l[e] = __float2bfloat16(vv[e] - __bfloat162float(h[e]));
    }
    __nv_bfloat16* dst = g_x2 + m * K2 + k4 * 4;
    *(uint2*)(dst)        = *(uint2*)h;
    *(uint2*)(dst + 1024) = *(uint2*)l;
    *(uint2*)(dst + 2048) = *(uint2*)h;
}

__global__ __launch_bounds__(256) void conv_w_kernel(
    const float* __restrict__ W0, const float* __restrict__ W1,
    const float* __restrict__ W2, const float* __restrict__ W3,
    const float* __restrict__ W4)
{
    size_t i4 = (size_t)blockIdx.x * 256 + threadIdx.x;
    size_t n = i4 >> 8;
    int k4 = (int)(i4 & 255);
    int wsel = (int)(n >> 10);
    const float* W = (wsel == 0) ? W0 : (wsel == 1) ? W1 : (wsel == 2) ? W2
                   : (wsel == 3) ? W3 : W4;
    float4 v = ((const float4*)(W + (n & 1023) * DIMM))[k4];
    __nv_bfloat16 h[4], l[4];
    float vv[4] = {v.x, v.y, v.z, v.w};
    #pragma unroll
    for (int e = 0; e < 4; e++) {
        h[e] = __float2bfloat16(vv[e]);
        l[e] = __float2bfloat16(vv[e] - __bfloat162float(h[e]));
    }
    __nv_bfloat16* dst = g_w2 + n * K2 + k4 * 4;
    *(uint2*)(dst)        = *(uint2*)h;
    *(uint2*)(dst + 1024) = *(uint2*)h;
    *(uint2*)(dst + 2048) = *(uint2*)l;
}

// ---------------- kernel 1: mma.sync bf16 projection GEMM ----------------
// C[16384,5120] = A'[16384,3072] x B'[5120,3072]^T, fp32 accum via HMMA.
// 128x128 tile, BK=32, 3-stage cp.async, 8 warps (2m x 4n), warp tile 64x32.
#define BK     32
#define NKIT   (K2/BK)               /* 96 */
#define LDS_ROW 80                   /* (32+8) bf16 = 80 bytes, conflict-free */
#define ATILE_B (128*LDS_ROW)        /* 10240 */
#define STG_B   (2*ATILE_B)          /* 20480 */
#define PROJ_SMEM (3*STG_B)          /* 61440 */

__global__ __launch_bounds__(256, 1) void proj_mma_kernel(
    const float* __restrict__ bq, const float* __restrict__ bk,
    const float* __restrict__ bv, const float* __restrict__ bb,
    const float* __restrict__ ba, float* __restrict__ alpha_out)
{
    extern __shared__ char dsm[];
    __shared__ float bias_s[128];
    const uint32_t sbase = s2u(dsm);
    const int tid = threadIdx.x;
    const int wid = tid >> 5, lane = tid & 31;
    const int nb = blockIdx.x, mb = blockIdx.y;
    const int wi = nb >> 3;
    const int m0 = mb * 128;
    const int r0g = nb * 128;
    const int r0  = (nb & 7) * 128;

    const float* bias = (wi == 0) ? bq : (wi == 1) ? bk : (wi == 2) ? bv
                       : (wi == 3) ? bb : ba;
    if (tid < 128) bias_s[tid] = bias[r0 + tid];

    // ---- load setup: each thread copies 2 A-chunks + 2 B-chunks (16B) per stage
    int ch0 = tid * 2;
    int arow0 = ch0 >> 2,        ac0 = (ch0 & 3);
    int arow1 = (ch0+1) >> 2,    ac1 = ((ch0+1) & 3);
    const char* aG0 = (const char*)(g_x2 + (size_t)(m0 + arow0) * K2) + ac0 * 16;
    const char* aG1 = (const char*)(g_x2 + (size_t)(m0 + arow1) * K2) + ac1 * 16;
    const char* bG0 = (const char*)(g_w2 + (size_t)(r0g + arow0) * K2) + ac0 * 16;
    const char* bG1 = (const char*)(g_w2 + (size_t)(r0g + arow1) * K2) + ac1 * 16;
    uint32_t aD0 = arow0 * LDS_ROW + ac0 * 16;
    uint32_t aD1 = arow1 * LDS_ROW + ac1 * 16;

    #define LOAD_STAGE(s, kit) do {                                     \
        uint32_t st = sbase + (s) * STG_B;                              \
        size_t kb = (size_t)(kit) * (BK * 2);                           \
        CP16(st + aD0,           aG0 + kb);                             \
        CP16(st + aD1,           aG1 + kb);                             \
        CP16(st + ATILE_B + aD0, bG0 + kb);                             \
        CP16(st + ATILE_B + aD1, bG1 + kb);                             \
    } while (0)

    // ---- mma fragment addressing
    const int warp_m = wid >> 2;          // 0..1
    const int warp_n = wid & 3;           // 0..3
    const int lr = lane & 15, lh = lane >> 4;
    const uint32_t aOff = (uint32_t)(warp_m * 64 + lr) * LDS_ROW + lh * 16;
    const uint32_t bOff = (uint32_t)(warp_n * 32 + lr) * LDS_ROW + lh * 16 + ATILE_B;

    float acc[4][4][4];
    #pragma unroll
    for (int i = 0; i < 4; i++)
        #pragma unroll
        for (int j = 0; j < 4; j++)
            #pragma unroll
            for (int e = 0; e < 4; e++) acc[i][j][e] = 0.0f;

    LOAD_STAGE(0, 0); CP_COMMIT();
    LOAD_STAGE(1, 1); CP_COMMIT();
    __syncthreads();

    #pragma unroll 1
    for (int i = 0; i < NKIT; i++) {
        CP_WAIT1();
        __syncthreads();
        if (i + 2 < NKIT) LOAD_STAGE((i + 2) % 3, i + 2);
        CP_COMMIT();

        const uint32_t st = sbase + (i % 3) * STG_B;
        #pragma unroll
        for (int ks = 0; ks < 2; ks++) {
            uint32_t af[4][4];
            #pragma unroll
            for (int mf = 0; mf < 4; mf++)
                LDM_X4(af[mf][0], af[mf][1], af[mf][2], af[mf][3],
                       st + aOff + mf * (16 * LDS_ROW) + ks * 32);
            uint32_t bf[2][4];
            #pragma unroll
            for (int nf = 0; nf < 2; nf++)
                LDM_X4(bf[nf][0], bf[nf][1], bf[nf][2], bf[nf][3],
                       st + bOff + nf * (16 * LDS_ROW) + ks * 32);
            #pragma unroll
            for (int mf = 0; mf < 4; mf++) {
                #pragma unroll
                for (int nf = 0; nf < 2; nf++) {
                    MMA16816(acc[mf][nf*2][0], acc[mf][nf*2][1],
                             acc[mf][nf*2][2], acc[mf][nf*2][3],
                             af[mf][0], af[mf][1], af[mf][2], af[mf][3],
                             bf[nf][0], bf[nf][2]);
                    MMA16816(acc[mf][nf*2+1][0], acc[mf][nf*2+1][1],
                             acc[mf][nf*2+1][2], acc[mf][nf*2+1][3],
                             af[mf][0], af[mf][1], af[mf][2], af[mf][3],
                             bf[nf][1], bf[nf][3]);
                }
            }
        }
    }

    // ---- epilogue
    float* dst0;
    if      (wi == 0) dst0 = g_q;
    else if (wi == 1) dst0 = g_k;
    else if (wi == 2) dst0 = g_v;
    else if (wi == 3) dst0 = g_bt;
    else              dst0 = g_la;

    const int g = lane >> 2, t4 = lane & 3;
    const int mBase = m0 + warp_m * 64;
    #pragma unroll
    for (int mf = 0; mf < 4; mf++) {
        #pragma unroll
        for (int nf = 0; nf < 4; nf++) {
            int nl = warp_n * 32 + nf * 8 + t4 * 2;    // local col in [0,128)
            float b0 = bias_s[nl], b1 = bias_s[nl + 1];
            #pragma unroll
            for (int half = 0; half < 2; half++) {
                int m = mBase + mf * 16 + g + half * 8;
                float v0 = acc[mf][nf][half*2 + 0] + b0;
                float v1 = acc[mf][nf][half*2 + 1] + b1;
                size_t off = (size_t)m * DIMM + r0 + nl;
                if (wi <= 1) {
                    *(float2*)(dst0 + off) = make_float2(v0*0.125f, v1*0.125f);
                } else if (wi == 2) {
                    *(float2*)(dst0 + off) = make_float2(v0, v1);
                } else if (wi == 3) {
                    *(float2*)(dst0 + off) = make_float2(softplusf(v0), softplusf(v1));
                } else {
                    float z0 = fminf(10.0f, fmaxf(-10.0f, v0));
                    float z1 = fminf(10.0f, fmaxf(-10.0f, v1));
                    *(float2*)(alpha_out + off) =
                        make_float2(1.0f/(1.0f+expf(-z0)), 1.0f/(1.0f+expf(-z1)));
                    *(float2*)(dst0 + off) =
                        make_float2(-softplusf(-z0), -softplusf(-z1));
                }
            }
        }
    }
}

// ---------------- kernel 2: per-chunk stats ----------------
__global__ __launch_bounds__(128) void stats_kernel()
{
    const int bid = blockIdx.x;
    const int c = threadIdx.x;
    const int h = bid & 15;
    const int n = (bid >> 4) & 31;
    const int b = bid >> 9;
    const int t = b * TLEN + n * CC + c;
    const int base = t * DIMM + h * HD;
    float sla = 0.0f, sb = 0.0f;
    #pragma unroll
    for (int d4 = 0; d4 < HD; d4 += 4) {
        float4 u = *(const float4*)(g_la + base + d4);
        float4 w = *(const float4*)(g_bt + base + d4);
        sla += u.x + u.y + u.z + u.w;
        sb  += w.x + w.y + w.z + w.w;
    }
    g_bm[bid * CC + c] = sb * (1.0f/64.0f);
    __shared__ float smem[CC];
    smem[c] = sla * (1.0f/64.0f);
    __syncthreads();
    #pragma unroll
    for (int off = 1; off < CC; off <<= 1) {
        float prev = (c >= off) ? smem[c - off] : 0.0f;
        __syncthreads();
        smem[c] += prev;
        __syncthreads();
    }
    g_m[bid * CC + c] = smem[c];
}

// ---------------- kernel 3: intra-chunk attention + delta ----------------
#define S3_QST 0
#define S3_KST (64*132)
#define S3_VBS (2*64*132)
#define S3_MS  (2*64*132 + 128*68)
#define S3_SS  (S3_MS + 128)
#define S3_FLOATS (S3_SS + 128*132)
#define S3_BYTES (S3_FLOATS * 4)

__global__ __launch_bounds__(256) void intra_kernel(float* __restrict__ y_out)
{
    extern __shared__ float sm[];
    float* qst = sm + S3_QST;
    float* kst = sm + S3_KST;
    float* vbs = sm + S3_VBS;
    float* ms  = sm + S3_MS;
    float* Ss  = sm + S3_SS;
    const int tid = threadIdx.x;
    const int bid = blockIdx.x;
    const int h = bid & 15;
    const int n = (bid >> 4) & 31;
    const int b = bid >> 9;
    const int tbase = b * TLEN + n * CC;

    #pragma unroll
    for (int it = 0; it < 8; it++) {
        int f  = tid + it * 256;
        int c  = f >> 4;
        int d4 = (f & 15) << 2;
        int g  = (tbase + c) * DIMM + h * HD + d4;
        float4 q4 = *(const float4*)(g_q  + g);
        float4 k4 = *(const float4*)(g_k  + g);
        float4 v4 = *(const float4*)(g_v  + g);
        float4 b4 = *(const float4*)(g_bt + g);
        qst[(d4+0)*132 + c] = q4.x; qst[(d4+1)*132 + c] = q4.y;
        qst[(d4+2)*132 + c] = q4.z; qst[(d4+3)*132 + c] = q4.w;
        kst[(d4+0)*132 + c] = k4.x; kst[(d4+1)*132 + c] = k4.y;
        kst[(d4+2)*132 + c] = k4.z; kst[(d4+3)*132 + c] = k4.w;
        *(float4*)(vbs + c*68 + d4) =
            make_float4(v4.x*b4.x, v4.y*b4.y, v4.z*b4.z, v4.w*b4.w);
    }
    if (tid < 128) ms[tid] = g_m[bid * CC + tid];
    __syncthreads();

    const int tx = tid & 15, ty = tid >> 4;
    float acc[8][8];
    #pragma unroll
    for (int i = 0; i < 8; i++)
        #pragma unroll
        for (int j = 0; j < 8; j++) acc[i][j] = 0.0f;
    #pragma unroll 8
    for (int kk = 0; kk < 64; kk++) {
        float a[8], bb2[8];
        *(float4*)&a[0]   = *(const float4*)&qst[kk*132 + ty*8];
        *(float4*)&a[4]   = *(const float4*)&qst[kk*132 + ty*8 + 4];
        *(float4*)&bb2[0] = *(const float4*)&kst[kk*132 + tx*8];
        *(float4*)&bb2[4] = *(const float4*)&kst[kk*132 + tx*8 + 4];
        #pragma unroll
        for (int i = 0; i < 8; i++)
            #pragma unroll
            for (int j = 0; j < 8; j++)
                acc[i][j] = fmaf(a[i], bb2[j], acc[i][j]);
    }
    float mi[8], mj[8];
    #pragma unroll
    for (int i = 0; i < 8; i++) mi[i] = ms[ty*8 + i];
    #pragma unroll
    for (int j = 0; j < 8; j++) mj[j] = ms[tx*8 + j];
    #pragma unroll
    for (int i = 0; i < 8; i++) {
        const int gi = ty*8 + i;
        float sv[8];
        #pragma unroll
        for (int j = 0; j < 8; j++) {
            const int gj = tx*8 + j;
            sv[j] = (gj <= gi) ? acc[i][j] * expf(mi[i] - mj[j]) : 0.0f;
        }
        *(float4*)&Ss[gi*132 + tx*8]     = make_float4(sv[0],sv[1],sv[2],sv[3]);
        *(float4*)&Ss[gi*132 + tx*8 + 4] = make_float4(sv[4],sv[5],sv[6],sv[7]);
    }
    __syncthreads();

    const int tx2 = tid & 7, ty2 = tid >> 3;
    const int i0 = ty2 * 4, dd0 = tx2 * 8;
    float y0[8], y1[8], y2[8], y3[8];
    #pragma unroll
    for (int e = 0; e < 8; e++) { y0[e]=0.f; y1[e]=0.f; y2[e]=0.f; y3[e]=0.f; }
    #pragma unroll 4
    for (int j = 0; j < CC; j++) {
        float s0 = Ss[(i0+0)*132 + j];
        float s1 = Ss[(i0+1)*132 + j];
        float s2 = Ss[(i0+2)*132 + j];
        float s3 = Ss[(i0+3)*132 + j];
        float vv[8];
        *(float4*)&vv[0] = *(const float4*)&vbs[j*68 + dd0];
        *(float4*)&vv[4] = *(const float4*)&vbs[j*68 + dd0 + 4];
        #pragma unroll
        for (int e = 0; e < 8; e++) {
            y0[e] = fmaf(s0, vv[e], y0[e]);
            y1[e] = fmaf(s1, vv[e], y1[e]);
            y2[e] = fmaf(s2, vv[e], y2[e]);
            y3[e] = fmaf(s3, vv[e], y3[e]);
        }
    }
    {
        int off = (tbase + i0 + 0) * DIMM + h * HD + dd0;
        *(float4*)(y_out + off)     = make_float4(y0[0],y0[1],y0[2],y0[3]);
        *(float4*)(y_out + off + 4) = make_float4(y0[4],y0[5],y0[6],y0[7]);
        off += DIMM;
        *(float4*)(y_out + off)     = make_float4(y1[0],y1[1],y1[2],y1[3]);
        *(float4*)(y_out + off + 4) = make_float4(y1[4],y1[5],y1[6],y1[7]);
        off += DIMM;
        *(float4*)(y_out + off)     = make_float4(y2[0],y2[1],y2[2],y2[3]);
        *(float4*)(y_out + off + 4) = make_float4(y2[4],y2[5],y2[6],y2[7]);
        off += DIMM;
        *(float4*)(y_out + off)     = make_float4(y3[0],y3[1],y3[2],y3[3]);
        *(float4*)(y_out + off + 4) = make_float4(y3[4],y3[5],y3[6],y3[7]);
    }

    // delta[kk][dd] = sum_c k[c,kk] * v[c,dd] * bm[c]
    __syncthreads();
    float* vbm = Ss;
    #pragma unroll
    for (int it = 0; it < 8; it++) {
        int f  = tid + it * 256;
        int c  = f >> 4;
        int d4 = (f & 15) << 2;
        float bmr = g_bm[bid * CC + c];
        float4 v4 = *(const float4*)(g_v + (tbase + c) * DIMM + h * HD + d4);
        *(float4*)(vbm + c*68 + d4) =
            make_float4(v4.x*bmr, v4.y*bmr, v4.z*bmr, v4.w*bmr);
    }
    __syncthreads();
    {
        const int dx = tid & 7, dy = tid >> 3;
        const int kk0 = dy * 2, ddo = dx * 8;
        float d0[8], d1[8];
        #pragma unroll
        for (int e = 0; e < 8; e++) { d0[e]=0.f; d1[e]=0.f; }
        #pragma unroll 4
        for (int c = 0; c < CC; c++) {
            float ka = kst[(kk0+0)*132 + c];
            float kb = kst[(kk0+1)*132 + c];
            float vv[8];
            *(float4*)&vv[0] = *(const float4*)&vbm[c*68 + ddo];
            *(float4*)&vv[4] = *(const float4*)&vbm[c*68 + ddo + 4];
            #pragma unroll
            for (int e = 0; e < 8; e++) {
                d0[e] = fmaf(ka, vv[e], d0[e]);
                d1[e] = fmaf(kb, vv[e], d1[e]);
            }
        }
        size_t dbase = (size_t)bid * 4096;
        *(float4*)(g_delta + dbase + (kk0+0)*64 + ddo)     = make_float4(d0[0],d0[1],d0[2],d0[3]);
        *(float4*)(g_delta + dbase + (kk0+0)*64 + ddo + 4) = make_float4(d0[4],d0[5],d0[6],d0[7]);
        *(float4*)(g_delta + dbase + (kk0+1)*64 + ddo)     = make_float4(d1[0],d1[1],d1[2],d1[3]);
        *(float4*)(g_delta + dbase + (kk0+1)*64 + ddo + 4) = make_float4(d1[4],d1[5],d1[6],d1[7]);
    }
}

// ---------------- kernel 4: state recurrence ----------------
__global__ __launch_bounds__(256) void recur_kernel(float* __restrict__ state_out)
{
    const int bh = blockIdx.x;
    const int b = bh >> 4, h = bh & 15;
    const int tid = threadIdx.x;
    float s[16];
    #pragma unroll
    for (int e = 0; e < 16; e++) s[e] = 0.0f;
    #pragma unroll 1
    for (int n = 0; n < NCH; n++) {
        const int cbid = (b * NCH + n) * HEADS + h;
        float asum = expf(g_m[cbid * CC + (CC - 1)]);
        size_t base = (size_t)cbid * 4096;
        #pragma unroll
        for (int e = 0; e < 16; e++) {
            int idx = tid + e * 256;
            g_stin[base + idx] = s[e];
            s[e] = s[e] * asum + g_delta[base + idx];
        }
    }
    size_t ob = (size_t)bh * 4096;
    #pragma unroll
    for (int e = 0; e < 16; e++) state_out[ob + tid + e * 256] = s[e];
}

// ---------------- kernel 5: y += (q @ state_in) * curve ----------------
__global__ __launch_bounds__(256) void ymem_kernel(float* __restrict__ y_out)
{
    __shared__ float qs[128*68];
    __shared__ float ss[64*68];
    __shared__ float cv[128];
    const int tid = threadIdx.x;
    const int bid = blockIdx.x;
    const int h = bid & 15;
    const int n = (bid >> 4) & 31;
    const int b = bid >> 9;
    const int tb = b * TLEN + n * CC;
    size_t sbase = (size_t)bid * 4096;

    #pragma unroll
    for (int it = 0; it < 8; it++) {
        int f = tid + it * 256;
        int c = f >> 4, d4 = (f & 15) << 2;
        *(float4*)(qs + c*68 + d4) =
            *(const float4*)(g_q + (tb + c) * DIMM + h * HD + d4);
    }
    #pragma unroll
    for (int it = 0; it < 4; it++) {
        int f = tid + it * 256;
        int kk = f >> 4, d4 = (f & 15) << 2;
        *(float4*)(ss + kk*68 + d4) = *(const float4*)(g_stin + sbase + kk*64 + d4);
    }
    if (tid < 128) cv[tid] = expf(g_m[bid * CC + tid]);
    __syncthreads();

    const int tx = tid & 7, ty = tid >> 3;
    const int c0 = ty * 4, dd0 = tx * 8;
    float a0[8], a1[8], a2[8], a3[8];
    #pragma unroll
    for (int e = 0; e < 8; e++) { a0[e]=0.f; a1[e]=0.f; a2[e]=0.f; a3[e]=0.f; }
    #pragma unroll 4
    for (int kk = 0; kk < 64; kk++) {
        float q0 = qs[(c0+0)*68 + kk];
        float q1 = qs[(c0+1)*68 + kk];
        float q2 = qs[(c0+2)*68 + kk];
        float q3 = qs[(c0+3)*68 + kk];
        float sv[8];
        *(float4*)&sv[0] = *(const float4*)&ss[kk*68 + dd0];
        *(float4*)&sv[4] = *(const float4*)&ss[kk*68 + dd0 + 4];
        #pragma unroll
        for (int e = 0; e < 8; e++) {
            a0[e] = fmaf(q0, sv[e], a0[e]);
            a1[e] = fmaf(q1, sv[e], a1[e]);
            a2[e] = fmaf(q2, sv[e], a2[e]);
            a3[e] = fmaf(q3, sv[e], a3[e]);
        }
    }
    #pragma unroll
    for (int i = 0; i < 4; i++) {
        float* ap = (i==0)?a0:(i==1)?a1:(i==2)?a2:a3;
        float cc = cv[c0 + i];
        size_t off = (size_t)(tb + c0 + i) * DIMM + h * HD + dd0;
        float4 o0 = *(float4*)(y_out + off);
        float4 o1 = *(float4*)(y_out + off + 4);
        o0.x += ap[0]*cc; o0.y += ap[1]*cc; o0.z += ap[2]*cc; o0.w += ap[3]*cc;
        o1.x += ap[4]*cc; o1.y += ap[5]*cc; o1.z += ap[6]*cc; o1.w += ap[7]*cc;
        *(float4*)(y_out + off)     = o0;
        *(float4*)(y_out + off + 4) = o1;
    }
}

// ---------------- launch ----------------
extern "C" void kernel_launch(void* const* d_in, const int* in_sizes, int n_in,
                              void* d_out, int out_size)
{
    (void)in_sizes; (void)n_in; (void)out_size;
    const float* x  = (const float*)d_in[0];
    const float* Wq = (const float*)d_in[1];
    const float* bq = (const float*)d_in[2];
    const float* Wk = (const float*)d_in[3];
    const float* bk = (const float*)d_in[4];
    const float* Wv = (const float*)d_in[5];
    const float* bv = (const float*)d_in[6];
    const float* Wb = (const float*)d_in[7];
    const float* bb = (const float*)d_in[8];
    const float* Wa = (const float*)d_in[9];
    const float* ba = (const float*)d_in[10];

    float* out       = (float*)d_out;
    float* y_out     = out;
    float* state_out = out + YN;
    float* alpha_out = out + YN + SN;

    cudaFuncSetAttribute(intra_kernel,
                         cudaFuncAttributeMaxDynamicSharedMemorySize, S3_BYTES);
    cudaFuncSetAttribute(proj_mma_kernel,
                         cudaFuncAttributeMaxDynamicSharedMemorySize, PROJ_SMEM);

    conv_x_kernel<<<MTOT * DIMM / 4 / 256, 256>>>(x);
    conv_w_kernel<<<NOUT * DIMM / 4 / 256, 256>>>(Wq, Wk, Wv, Wb, Wa);
    dim3 g1(40, 128);
    proj_mma_kernel<<<g1, 256, PROJ_SMEM>>>(bq, bk, bv, bb, ba, alpha_out);
    stats_kernel<<<BSZ*NCH*HEADS, 128>>>();
    intra_kernel<<<BSZ*NCH*HEADS, 256, S3_BYTES>>>(y_out);
    recur_kernel<<<BSZ*HEADS, 256>>>(state_out);
    ymem_kernel<<<BSZ*NCH*HEADS, 256>>>(y_out);
}

// round 8
// speedup vs baseline: 2.7311x; 1.5644x over previous
#include <cuda_runtime.h>
#include <cuda_bf16.h>
#include <cuda_fp16.h>
#include <math.h>
#include <stdint.h>

#define DIMM   1024
#define HEADS  16
#define HD     64
#define CC     128
#define BSZ    4
#define TLEN   4096
#define NCH    (TLEN/CC)        /* 32 */
#define MTOT   (BSZ*TLEN)       /* 16384 */
#define K2     3072             /* max split K dim (alpha) */
#define NOUT   5120             /* 5 matrices x 1024 */

#define YN  (MTOT*DIMM)
#define SN  (BSZ*HEADS*HD*HD)

// ---------------- scratch ----------------
__device__ float g_q [MTOT*DIMM];
__device__ float g_k [MTOT*DIMM];
__device__ float g_v [MTOT*DIMM];
__device__ float g_bt[MTOT*DIMM];
__device__ float g_la[MTOT*DIMM];
__device__ float g_m [BSZ*NCH*HEADS*CC];
__device__ float g_bm[BSZ*NCH*HEADS*CC];
__device__ __half g_x2[(size_t)MTOT*K2];   // [M,3072] = [hi|lo|hi] fp16
__device__ __half g_w2[(size_t)NOUT*K2];   // qkvb: [hi|-|-]; alpha: [hi|hi|lo]
__device__ float g_delta[(size_t)BSZ*NCH*HEADS*HD*HD];
__device__ float g_stin [(size_t)BSZ*NCH*HEADS*HD*HD];

__device__ __forceinline__ float softplusf(float x) {
    return fmaxf(x, 0.0f) + log1pf(expf(-fabsf(x)));
}
__device__ __forceinline__ uint32_t s2u(const void* p) {
    uint32_t a;
    asm("{ .reg .u64 t; cvta.to.shared.u64 t, %1; cvt.u32.u64 %0, t; }"
        : "=r"(a) : "l"(p));
    return a;
}
#define CP16(dst,src) asm volatile("cp.async.cg.shared.global [%0], [%1], 16;" ::"r"(dst),"l"(src):"memory")
#define CP_COMMIT()   asm volatile("cp.async.commit_group;" :::"memory")
#define CP_WAIT1()    asm volatile("cp.async.wait_group 1;" :::"memory")

#define LDM_X4(r0,r1,r2,r3,addr) \
    asm volatile("ldmatrix.sync.aligned.m8n8.x4.shared.b16 {%0,%1,%2,%3}, [%4];" \
        : "=r"(r0),"=r"(r1),"=r"(r2),"=r"(r3) : "r"(addr))

#define MMA16816(d0,d1,d2,d3,a0,a1,a2,a3,b0,b1) \
    asm volatile("mma.sync.aligned.m16n8k16.row.col.f32.f16.f16.f32 " \
        "{%0,%1,%2,%3}, {%4,%5,%6,%7}, {%8,%9}, {%0,%1,%2,%3};" \
        : "+f"(d0),"+f"(d1),"+f"(d2),"+f"(d3) \
        : "r"(a0),"r"(a1),"r"(a2),"r"(a3),"r"(b0),"r"(b1))

// ---------------- conversion kernels ----------------
__global__ __launch_bounds__(256) void conv_x_kernel(const float* __restrict__ x)
{
    size_t i4 = (size_t)blockIdx.x * 256 + threadIdx.x;
    float4 v = ((const float4*)x)[i4];
    size_t m = i4 >> 8;
    int k4 = (int)(i4 & 255);
    __half h[4], l[4];
    float vv[4] = {v.x, v.y, v.z, v.w};
    #pragma unroll
    for (int e = 0; e < 4; e++) {
        h[e] = __float2half_rn(vv[e]);
        l[e] = __float2half_rn(vv[e] - __half2float(h[e]));
    }
    __half* dst = g_x2 + m * K2 + k4 * 4;
    *(uint2*)(dst)        = *(uint2*)h;
    *(uint2*)(dst + 1024) = *(uint2*)l;
    *(uint2*)(dst + 2048) = *(uint2*)h;
}

__global__ __launch_bounds__(256) void conv_w_kernel(
    const float* __restrict__ W0, const float* __restrict__ W1,
    const float* __restrict__ W2, const float* __restrict__ W3,
    const float* __restrict__ W4)
{
    size_t i4 = (size_t)blockIdx.x * 256 + threadIdx.x;
    size_t n = i4 >> 8;
    int k4 = (int)(i4 & 255);
    int wsel = (int)(n >> 10);
    const float* W = (wsel == 0) ? W0 : (wsel == 1) ? W1 : (wsel == 2) ? W2
                   : (wsel == 3) ? W3 : W4;
    float4 v = ((const float4*)(W + (n & 1023) * DIMM))[k4];
    __half h[4], l[4];
    float vv[4] = {v.x, v.y, v.z, v.w};
    #pragma unroll
    for (int e = 0; e < 4; e++) {
        h[e] = __float2half_rn(vv[e]);
        l[e] = __float2half_rn(vv[e] - __half2float(h[e]));
    }
    __half* dst = g_w2 + n * K2 + k4 * 4;
    *(uint2*)(dst) = *(uint2*)h;
    if (wsel == 4) {
        *(uint2*)(dst + 1024) = *(uint2*)h;
        *(uint2*)(dst + 2048) = *(uint2*)l;
    }
}

// ---------------- kernel 1: mma.sync fp16 projection GEMM ----------------
// q,k,v,beta: K=1024 plain fp16; alpha: K=3072 split [hi|lo|hi]x[hi|hi|lo].
// 128x128 tile, BK=32, 3-stage cp.async, 8 warps (2m x 4n), warp tile 64x32.
#define BK     32
#define LDS_ROW 80                   /* (32+8)*2B, conflict-free ldmatrix */
#define ATILE_B (128*LDS_ROW)
#define STG_B   (2*ATILE_B)
#define PROJ_SMEM (3*STG_B)          /* 61440 */

__global__ __launch_bounds__(256, 1) void proj_mma_kernel(
    const float* __restrict__ bq, const float* __restrict__ bk,
    const float* __restrict__ bv, const float* __restrict__ bb,
    const float* __restrict__ ba, float* __restrict__ alpha_out)
{
    extern __shared__ char dsm[];
    __shared__ float bias_s[128];
    const uint32_t sbase = s2u(dsm);
    const int tid = threadIdx.x;
    const int wid = tid >> 5, lane = tid & 31;
    const int nb = blockIdx.x, mb = blockIdx.y;
    const int wi = nb >> 3;
    const int nkit = (wi == 4) ? (K2 / BK) : (DIMM / BK);   // 96 or 32
    const int m0 = mb * 128;
    const int r0g = nb * 128;
    const int r0  = (nb & 7) * 128;

    const float* bias = (wi == 0) ? bq : (wi == 1) ? bk : (wi == 2) ? bv
                       : (wi == 3) ? bb : ba;
    if (tid < 128) bias_s[tid] = bias[r0 + tid];

    // ---- load setup: each thread copies 2 A-chunks + 2 B-chunks (16B) per stage
    int ch0 = tid * 2;
    int arow0 = ch0 >> 2,        ac0 = (ch0 & 3);
    int arow1 = (ch0+1) >> 2,    ac1 = ((ch0+1) & 3);
    const char* aG0 = (const char*)(g_x2 + (size_t)(m0 + arow0) * K2) + ac0 * 16;
    const char* aG1 = (const char*)(g_x2 + (size_t)(m0 + arow1) * K2) + ac1 * 16;
    const char* bG0 = (const char*)(g_w2 + (size_t)(r0g + arow0) * K2) + ac0 * 16;
    const char* bG1 = (const char*)(g_w2 + (size_t)(r0g + arow1) * K2) + ac1 * 16;
    uint32_t aD0 = arow0 * LDS_ROW + ac0 * 16;
    uint32_t aD1 = arow1 * LDS_ROW + ac1 * 16;

    #define LOAD_STAGE(s, kit) do {                                     \
        uint32_t st = sbase + (s) * STG_B;                              \
        size_t kb = (size_t)(kit) * (BK * 2);                           \
        CP16(st + aD0,           aG0 + kb);                             \
        CP16(st + aD1,           aG1 + kb);                             \
        CP16(st + ATILE_B + aD0, bG0 + kb);                             \
        CP16(st + ATILE_B + aD1, bG1 + kb);                             \
    } while (0)

    // ---- mma fragment addressing
    const int warp_m = wid >> 2;
    const int warp_n = wid & 3;
    const int lr = lane & 15, lh = lane >> 4;
    const uint32_t aOff = (uint32_t)(warp_m * 64 + lr) * LDS_ROW + lh * 16;
    const uint32_t bOff = (uint32_t)(warp_n * 32 + lr) * LDS_ROW + lh * 16 + ATILE_B;

    float acc[4][4][4];
    #pragma unroll
    for (int i = 0; i < 4; i++)
        #pragma unroll
        for (int j = 0; j < 4; j++)
            #pragma unroll
            for (int e = 0; e < 4; e++) acc[i][j][e] = 0.0f;

    LOAD_STAGE(0, 0); CP_COMMIT();
    LOAD_STAGE(1, 1); CP_COMMIT();
    __syncthreads();

    #pragma unroll 1
    for (int i = 0; i < nkit; i++) {
        CP_WAIT1();
        __syncthreads();
        if (i + 2 < nkit) LOAD_STAGE((i + 2) % 3, i + 2);
        CP_COMMIT();

        const uint32_t st = sbase + (i % 3) * STG_B;
        #pragma unroll
        for (int ks = 0; ks < 2; ks++) {
            uint32_t af[4][4];
            #pragma unroll
            for (int mf = 0; mf < 4; mf++)
                LDM_X4(af[mf][0], af[mf][1], af[mf][2], af[mf][3],
                       st + aOff + mf * (16 * LDS_ROW) + ks * 32);
            uint32_t bf[2][4];
            #pragma unroll
            for (int nf = 0; nf < 2; nf++)
                LDM_X4(bf[nf][0], bf[nf][1], bf[nf][2], bf[nf][3],
                       st + bOff + nf * (16 * LDS_ROW) + ks * 32);
            #pragma unroll
            for (int mf = 0; mf < 4; mf++) {
                #pragma unroll
                for (int nf = 0; nf < 2; nf++) {
                    MMA16816(acc[mf][nf*2][0], acc[mf][nf*2][1],
                             acc[mf][nf*2][2], acc[mf][nf*2][3],
                             af[mf][0], af[mf][1], af[mf][2], af[mf][3],
                             bf[nf][0], bf[nf][2]);
                    MMA16816(acc[mf][nf*2+1][0], acc[mf][nf*2+1][1],
                             acc[mf][nf*2+1][2], acc[mf][nf*2+1][3],
                             af[mf][0], af[mf][1], af[mf][2], af[mf][3],
                             bf[nf][1], bf[nf][3]);
                }
            }
        }
    }

    // ---- epilogue
    float* dst0;
    if      (wi == 0) dst0 = g_q;
    else if (wi == 1) dst0 = g_k;
    else if (wi == 2) dst0 = g_v;
    else if (wi == 3) dst0 = g_bt;
    else              dst0 = g_la;

    const int g = lane >> 2, t4 = lane & 3;
    const int mBase = m0 + warp_m * 64;
    #pragma unroll
    for (int mf = 0; mf < 4; mf++) {
        #pragma unroll
        for (int nf = 0; nf < 4; nf++) {
            int nl = warp_n * 32 + nf * 8 + t4 * 2;
            float b0 = bias_s[nl], b1 = bias_s[nl + 1];
            #pragma unroll
            for (int half = 0; half < 2; half++) {
                int m = mBase + mf * 16 + g + half * 8;
                float v0 = acc[mf][nf][half*2 + 0] + b0;
                float v1 = acc[mf][nf][half*2 + 1] + b1;
                size_t off = (size_t)m * DIMM + r0 + nl;
                if (wi <= 1) {
                    *(float2*)(dst0 + off) = make_float2(v0*0.125f, v1*0.125f);
                } else if (wi == 2) {
                    *(float2*)(dst0 + off) = make_float2(v0, v1);
                } else if (wi == 3) {
                    *(float2*)(dst0 + off) = make_float2(softplusf(v0), softplusf(v1));
                } else {
                    float z0 = fminf(10.0f, fmaxf(-10.0f, v0));
                    float z1 = fminf(10.0f, fmaxf(-10.0f, v1));
                    *(float2*)(alpha_out + off) =
                        make_float2(1.0f/(1.0f+expf(-z0)), 1.0f/(1.0f+expf(-z1)));
                    *(float2*)(dst0 + off) =
                        make_float2(-softplusf(-z0), -softplusf(-z1));
                }
            }
        }
    }
}

// ---------------- kernel 2: per-chunk stats ----------------
__global__ __launch_bounds__(128) void stats_kernel()
{
    const int bid = blockIdx.x;
    const int c = threadIdx.x;
    const int h = bid & 15;
    const int n = (bid >> 4) & 31;
    const int b = bid >> 9;
    const int t = b * TLEN + n * CC + c;
    const int base = t * DIMM + h * HD;
    float sla = 0.0f, sb = 0.0f;
    #pragma unroll
    for (int d4 = 0; d4 < HD; d4 += 4) {
        float4 u = *(const float4*)(g_la + base + d4);
        float4 w = *(const float4*)(g_bt + base + d4);
        sla += u.x + u.y + u.z + u.w;
        sb  += w.x + w.y + w.z + w.w;
    }
    g_bm[bid * CC + c] = sb * (1.0f/64.0f);
    __shared__ float smem[CC];
    smem[c] = sla * (1.0f/64.0f);
    __syncthreads();
    #pragma unroll
    for (int off = 1; off < CC; off <<= 1) {
        float prev = (c >= off) ? smem[c - off] : 0.0f;
        __syncthreads();
        smem[c] += prev;
        __syncthreads();
    }
    g_m[bid * CC + c] = smem[c];
}

// ---------------- kernel 3: intra-chunk attention + delta ----------------
#define S3_QST 0
#define S3_KST (64*132)
#define S3_VBS (2*64*132)
#define S3_MS  (2*64*132 + 128*68)
#define S3_SS  (S3_MS + 128)
#define S3_FLOATS (S3_SS + 128*132)
#define S3_BYTES (S3_FLOATS * 4)

__global__ __launch_bounds__(256) void intra_kernel(float* __restrict__ y_out)
{
    extern __shared__ float sm[];
    float* qst = sm + S3_QST;
    float* kst = sm + S3_KST;
    float* vbs = sm + S3_VBS;
    float* ms  = sm + S3_MS;
    float* Ss  = sm + S3_SS;
    const int tid = threadIdx.x;
    const int bid = blockIdx.x;
    const int h = bid & 15;
    const int n = (bid >> 4) & 31;
    const int b = bid >> 9;
    const int tbase = b * TLEN + n * CC;

    #pragma unroll
    for (int it = 0; it < 8; it++) {
        int f  = tid + it * 256;
        int c  = f >> 4;
        int d4 = (f & 15) << 2;
        int g  = (tbase + c) * DIMM + h * HD + d4;
        float4 q4 = *(const float4*)(g_q  + g);
        float4 k4 = *(const float4*)(g_k  + g);
        float4 v4 = *(const float4*)(g_v  + g);
        float4 b4 = *(const float4*)(g_bt + g);
        qst[(d4+0)*132 + c] = q4.x; qst[(d4+1)*132 + c] = q4.y;
        qst[(d4+2)*132 + c] = q4.z; qst[(d4+3)*132 + c] = q4.w;
        kst[(d4+0)*132 + c] = k4.x; kst[(d4+1)*132 + c] = k4.y;
        kst[(d4+2)*132 + c] = k4.z; kst[(d4+3)*132 + c] = k4.w;
        *(float4*)(vbs + c*68 + d4) =
            make_float4(v4.x*b4.x, v4.y*b4.y, v4.z*b4.z, v4.w*b4.w);
    }
    if (tid < 128) ms[tid] = g_m[bid * CC + tid];
    __syncthreads();

    const int tx = tid & 15, ty = tid >> 4;
    float acc[8][8];
    #pragma unroll
    for (int i = 0; i < 8; i++)
        #pragma unroll
        for (int j = 0; j < 8; j++) acc[i][j] = 0.0f;
    #pragma unroll 8
    for (int kk = 0; kk < 64; kk++) {
        float a[8], bb2[8];
        *(float4*)&a[0]   = *(const float4*)&qst[kk*132 + ty*8];
        *(float4*)&a[4]   = *(const float4*)&qst[kk*132 + ty*8 + 4];
        *(float4*)&bb2[0] = *(const float4*)&kst[kk*132 + tx*8];
        *(float4*)&bb2[4] = *(const float4*)&kst[kk*132 + tx*8 + 4];
        #pragma unroll
        for (int i = 0; i < 8; i++)
            #pragma unroll
            for (int j = 0; j < 8; j++)
                acc[i][j] = fmaf(a[i], bb2[j], acc[i][j]);
    }
    float mi[8], mj[8];
    #pragma unroll
    for (int i = 0; i < 8; i++) mi[i] = ms[ty*8 + i];
    #pragma unroll
    for (int j = 0; j < 8; j++) mj[j] = ms[tx*8 + j];
    #pragma unroll
    for (int i = 0; i < 8; i++) {
        const int gi = ty*8 + i;
        float sv[8];
        #pragma unroll
        for (int j = 0; j < 8; j++) {
            const int gj = tx*8 + j;
            sv[j] = (gj <= gi) ? acc[i][j] * expf(mi[i] - mj[j]) : 0.0f;
        }
        *(float4*)&Ss[gi*132 + tx*8]     = make_float4(sv[0],sv[1],sv[2],sv[3]);
        *(float4*)&Ss[gi*132 + tx*8 + 4] = make_float4(sv[4],sv[5],sv[6],sv[7]);
    }
    __syncthreads();

    const int tx2 = tid & 7, ty2 = tid >> 3;
    const int i0 = ty2 * 4, dd0 = tx2 * 8;
    float y0[8], y1[8], y2[8], y3[8];
    #pragma unroll
    for (int e = 0; e < 8; e++) { y0[e]=0.f; y1[e]=0.f; y2[e]=0.f; y3[e]=0.f; }
    #pragma unroll 4
    for (int j = 0; j < CC; j++) {
        float s0 = Ss[(i0+0)*132 + j];
        float s1 = Ss[(i0+1)*132 + j];
        float s2 = Ss[(i0+2)*132 + j];
        float s3 = Ss[(i0+3)*132 + j];
        float vv[8];
        *(float4*)&vv[0] = *(const float4*)&vbs[j*68 + dd0];
        *(float4*)&vv[4] = *(const float4*)&vbs[j*68 + dd0 + 4];
        #pragma unroll
        for (int e = 0; e < 8; e++) {
            y0[e] = fmaf(s0, vv[e], y0[e]);
            y1[e] = fmaf(s1, vv[e], y1[e]);
            y2[e] = fmaf(s2, vv[e], y2[e]);
            y3[e] = fmaf(s3, vv[e], y3[e]);
        }
    }
    {
        int off = (tbase + i0 + 0) * DIMM + h * HD + dd0;
        *(float4*)(y_out + off)     = make_float4(y0[0],y0[1],y0[2],y0[3]);
        *(float4*)(y_out + off + 4) = make_float4(y0[4],y0[5],y0[6],y0[7]);
        off += DIMM;
        *(float4*)(y_out + off)     = make_float4(y1[0],y1[1],y1[2],y1[3]);
        *(float4*)(y_out + off + 4) = make_float4(y1[4],y1[5],y1[6],y1[7]);
        off += DIMM;
        *(float4*)(y_out + off)     = make_float4(y2[0],y2[1],y2[2],y2[3]);
        *(float4*)(y_out + off + 4) = make_float4(y2[4],y2[5],y2[6],y2[7]);
        off += DIMM;
        *(float4*)(y_out + off)     = make_float4(y3[0],y3[1],y3[2],y3[3]);
        *(float4*)(y_out + off + 4) = make_float4(y3[4],y3[5],y3[6],y3[7]);
    }

    // delta[kk][dd] = sum_c k[c,kk] * v[c,dd] * bm[c]
    __syncthreads();
    float* vbm = Ss;
    #pragma unroll
    for (int it = 0; it < 8; it++) {
        int f  = tid + it * 256;
        int c  = f >> 4;
        int d4 = (f & 15) << 2;
        float bmr = g_bm[bid * CC + c];
        float4 v4 = *(const float4*)(g_v + (tbase + c) * DIMM + h * HD + d4);
        *(float4*)(vbm + c*68 + d4) =
            make_float4(v4.x*bmr, v4.y*bmr, v4.z*bmr, v4.w*bmr);
    }
    __syncthreads();
    {
        const int dx = tid & 7, dy = tid >> 3;
        const int kk0 = dy * 2, ddo = dx * 8;
        float d0[8], d1[8];
        #pragma unroll
        for (int e = 0; e < 8; e++) { d0[e]=0.f; d1[e]=0.f; }
        #pragma unroll 4
        for (int c = 0; c < CC; c++) {
            float ka = kst[(kk0+0)*132 + c];
            float kb = kst[(kk0+1)*132 + c];
            float vv[8];
            *(float4*)&vv[0] = *(const float4*)&vbm[c*68 + ddo];
            *(float4*)&vv[4] = *(const float4*)&vbm[c*68 + ddo + 4];
            #pragma unroll
            for (int e = 0; e < 8; e++) {
                d0[e] = fmaf(ka, vv[e], d0[e]);
                d1[e] = fmaf(kb, vv[e], d1[e]);
            }
        }
        size_t dbase = (size_t)bid * 4096;
        *(float4*)(g_delta + dbase + (kk0+0)*64 + ddo)     = make_float4(d0[0],d0[1],d0[2],d0[3]);
        *(float4*)(g_delta + dbase + (kk0+0)*64 + ddo + 4) = make_float4(d0[4],d0[5],d0[6],d0[7]);
        *(float4*)(g_delta + dbase + (kk0+1)*64 + ddo)     = make_float4(d1[0],d1[1],d1[2],d1[3]);
        *(float4*)(g_delta + dbase + (kk0+1)*64 + ddo + 4) = make_float4(d1[4],d1[5],d1[6],d1[7]);
    }
}

// ---------------- kernel 4: state recurrence ----------------
__global__ __launch_bounds__(256) void recur_kernel(float* __restrict__ state_out)
{
    const int bh = blockIdx.x;
    const int b = bh >> 4, h = bh & 15;
    const int tid = threadIdx.x;
    float s[16];
    #pragma unroll
    for (int e = 0; e < 16; e++) s[e] = 0.0f;
    #pragma unroll 1
    for (int n = 0; n < NCH; n++) {
        const int cbid = (b * NCH + n) * HEADS + h;
        float asum = expf(g_m[cbid * CC + (CC - 1)]);
        size_t base = (size_t)cbid * 4096;
        #pragma unroll
        for (int e = 0; e < 16; e++) {
            int idx = tid + e * 256;
            g_stin[base + idx] = s[e];
            s[e] = s[e] * asum + g_delta[base + idx];
        }
    }
    size_t ob = (size_t)bh * 4096;
    #pragma unroll
    for (int e = 0; e < 16; e++) state_out[ob + tid + e * 256] = s[e];
}

// ---------------- kernel 5: y += (q @ state_in) * curve ----------------
__global__ __launch_bounds__(256) void ymem_kernel(float* __restrict__ y_out)
{
    __shared__ float qs[128*68];
    __shared__ float ss[64*68];
    __shared__ float cv[128];
    const int tid = threadIdx.x;
    const int bid = blockIdx.x;
    const int h = bid & 15;
    const int n = (bid >> 4) & 31;
    const int b = bid >> 9;
    const int tb = b * TLEN + n * CC;
    size_t sbase = (size_t)bid * 4096;

    #pragma unroll
    for (int it = 0; it < 8; it++) {
        int f = tid + it * 256;
        int c = f >> 4, d4 = (f & 15) << 2;
        *(float4*)(qs + c*68 + d4) =
            *(const float4*)(g_q + (tb + c) * DIMM + h * HD + d4);
    }
    #pragma unroll
    for (int it = 0; it < 4; it++) {
        int f = tid + it * 256;
        int kk = f >> 4, d4 = (f & 15) << 2;
        *(float4*)(ss + kk*68 + d4) = *(const float4*)(g_stin + sbase + kk*64 + d4);
    }
    if (tid < 128) cv[tid] = expf(g_m[bid * CC + tid]);
    __syncthreads();

    const int tx = tid & 7, ty = tid >> 3;
    const int c0 = ty * 4, dd0 = tx * 8;
    float a0[8], a1[8], a2[8], a3[8];
    #pragma unroll
    for (int e = 0; e < 8; e++) { a0[e]=0.f; a1[e]=0.f; a2[e]=0.f; a3[e]=0.f; }
    #pragma unroll 4
    for (int kk = 0; kk < 64; kk++) {
        float q0 = qs[(c0+0)*68 + kk];
        float q1 = qs[(c0+1)*68 + kk];
        float q2 = qs[(c0+2)*68 + kk];
        float q3 = qs[(c0+3)*68 + kk];
        float sv[8];
        *(float4*)&sv[0] = *(const float4*)&ss[kk*68 + dd0];
        *(float4*)&sv[4] = *(const float4*)&ss[kk*68 + dd0 + 4];
        #pragma unroll
        for (int e = 0; e < 8; e++) {
            a0[e] = fmaf(q0, sv[e], a0[e]);
            a1[e] = fmaf(q1, sv[e], a1[e]);
            a2[e] = fmaf(q2, sv[e], a2[e]);
            a3[e] = fmaf(q3, sv[e], a3[e]);
        }
    }
    #pragma unroll
    for (int i = 0; i < 4; i++) {
        float* ap = (i==0)?a0:(i==1)?a1:(i==2)?a2:a3;
        float cc = cv[c0 + i];
        size_t off = (size_t)(tb + c0 + i) * DIMM + h * HD + dd0;
        float4 o0 = *(float4*)(y_out + off);
        float4 o1 = *(float4*)(y_out + off + 4);
        o0.x += ap[0]*cc; o0.y += ap[1]*cc; o0.z += ap[2]*cc; o0.w += ap[3]*cc;
        o1.x += ap[4]*cc; o1.y += ap[5]*cc; o1.z += ap[6]*cc; o1.w += ap[7]*cc;
        *(float4*)(y_out + off)     = o0;
        *(float4*)(y_out + off + 4) = o1;
    }
}

// ---------------- launch ----------------
extern "C" void kernel_launch(void* const* d_in, const int* in_sizes, int n_in,
                              void* d_out, int out_size)
{
    (void)in_sizes; (void)n_in; (void)out_size;
    const float* x  = (const float*)d_in[0];
    const float* Wq = (const float*)d_in[1];
    const float* bq = (const float*)d_in[2];
    const float* Wk = (const float*)d_in[3];
    const float* bk = (const float*)d_in[4];
    const float* Wv = (const float*)d_in[5];
    const float* bv = (const float*)d_in[6];
    const float* Wb = (const float*)d_in[7];
    const float* bb = (const float*)d_in[8];
    const float* Wa = (const float*)d_in[9];
    const float* ba = (const float*)d_in[10];

    float* out       = (float*)d_out;
    float* y_out     = out;
    float* state_out = out + YN;
    float* alpha_out = out + YN + SN;

    cudaFuncSetAttribute(intra_kernel,
                         cudaFuncAttributeMaxDynamicSharedMemorySize, S3_BYTES);
    cudaFuncSetAttribute(proj_mma_kernel,
                         cudaFuncAttributeMaxDynamicSharedMemorySize, PROJ_SMEM);

    conv_x_kernel<<<MTOT * DIMM / 4 / 256, 256>>>(x);
    conv_w_kernel<<<NOUT * DIMM / 4 / 256, 256>>>(Wq, Wk, Wv, Wb, Wa);
    dim3 g1(40, 128);
    proj_mma_kernel<<<g1, 256, PROJ_SMEM>>>(bq, bk, bv, bb, ba, alpha_out);
    stats_kernel<<<BSZ*NCH*HEADS, 128>>>();
    intra_kernel<<<BSZ*NCH*HEADS, 256, S3_BYTES>>>(y_out);
    recur_kernel<<<BSZ*HEADS, 256>>>(state_out);
    ymem_kernel<<<BSZ*NCH*HEADS, 256>>>(y_out);
}

// round 9
// speedup vs baseline: 3.4639x; 1.2683x over previous
#include <cuda_runtime.h>
#include <cuda_bf16.h>
#include <cuda_fp16.h>
#include <math.h>
#include <stdint.h>

#define DIMM   1024
#define HEADS  16
#define HD     64
#define CC     128
#define BSZ    4
#define TLEN   4096
#define NCH    (TLEN/CC)        /* 32 */
#define MTOT   (BSZ*TLEN)       /* 16384 */
#define K2     3072             /* max split K dim (alpha) */
#define NOUT   5120             /* 5 matrices x 1024 */

#define YN  (MTOT*DIMM)
#define SN  (BSZ*HEADS*HD*HD)

// ---------------- scratch ----------------
__device__ float g_q [MTOT*DIMM];           // fp32 q (ymem)
__device__ float g_bt[MTOT*DIMM];           // fp32 softplus(beta) (stats)
__device__ float g_la[MTOT*DIMM];           // log_sigmoid(alpha) (stats)
__device__ __half g_qh[MTOT*DIMM];          // fp16 copies for intra mma
__device__ __half g_kh[MTOT*DIMM];
__device__ __half g_vh[MTOT*DIMM];
__device__ __half g_bh[MTOT*DIMM];
__device__ float g_m [BSZ*NCH*HEADS*CC];
__device__ float g_bm[BSZ*NCH*HEADS*CC];
__device__ __half g_x2[(size_t)MTOT*K2];    // [M,3072] = [hi|lo|hi] fp16
__device__ __half g_w2[(size_t)NOUT*K2];    // qkvb: [hi|-|-]; alpha: [hi|hi|lo]
__device__ float g_delta[(size_t)BSZ*NCH*HEADS*HD*HD];
__device__ float g_stin [(size_t)BSZ*NCH*HEADS*HD*HD];

__device__ __forceinline__ float softplusf(float x) {
    return fmaxf(x, 0.0f) + log1pf(expf(-fabsf(x)));
}
__device__ __forceinline__ uint32_t s2u(const void* p) {
    uint32_t a;
    asm("{ .reg .u64 t; cvta.to.shared.u64 t, %1; cvt.u32.u64 %0, t; }"
        : "=r"(a) : "l"(p));
    return a;
}
__device__ __forceinline__ uint32_t f22h(float a, float b) {
    __half2 h = __floats2half2_rn(a, b);
    return *(uint32_t*)&h;
}
#define CP16(dst,src) asm volatile("cp.async.cg.shared.global [%0], [%1], 16;" ::"r"(dst),"l"(src):"memory")
#define CP_COMMIT()   asm volatile("cp.async.commit_group;" :::"memory")
#define CP_WAIT1()    asm volatile("cp.async.wait_group 1;" :::"memory")

#define LDM_X4(r0,r1,r2,r3,addr) \
    asm volatile("ldmatrix.sync.aligned.m8n8.x4.shared.b16 {%0,%1,%2,%3}, [%4];" \
        : "=r"(r0),"=r"(r1),"=r"(r2),"=r"(r3) : "r"(addr))

#define LDM_X4T(r0,r1,r2,r3,addr) \
    asm volatile("ldmatrix.sync.aligned.m8n8.x4.trans.shared.b16 {%0,%1,%2,%3}, [%4];" \
        : "=r"(r0),"=r"(r1),"=r"(r2),"=r"(r3) : "r"(addr))

#define MMA16816(d0,d1,d2,d3,a0,a1,a2,a3,b0,b1) \
    asm volatile("mma.sync.aligned.m16n8k16.row.col.f32.f16.f16.f32 " \
        "{%0,%1,%2,%3}, {%4,%5,%6,%7}, {%8,%9}, {%0,%1,%2,%3};" \
        : "+f"(d0),"+f"(d1),"+f"(d2),"+f"(d3) \
        : "r"(a0),"r"(a1),"r"(a2),"r"(a3),"r"(b0),"r"(b1))

// ---------------- conversion kernels ----------------
__global__ __launch_bounds__(256) void conv_x_kernel(const float* __restrict__ x)
{
    size_t i4 = (size_t)blockIdx.x * 256 + threadIdx.x;
    float4 v = ((const float4*)x)[i4];
    size_t m = i4 >> 8;
    int k4 = (int)(i4 & 255);
    __half h[4], l[4];
    float vv[4] = {v.x, v.y, v.z, v.w};
    #pragma unroll
    for (int e = 0; e < 4; e++) {
        h[e] = __float2half_rn(vv[e]);
        l[e] = __float2half_rn(vv[e] - __half2float(h[e]));
    }
    __half* dst = g_x2 + m * K2 + k4 * 4;
    *(uint2*)(dst)        = *(uint2*)h;
    *(uint2*)(dst + 1024) = *(uint2*)l;
    *(uint2*)(dst + 2048) = *(uint2*)h;
}

__global__ __launch_bounds__(256) void conv_w_kernel(
    const float* __restrict__ W0, const float* __restrict__ W1,
    const float* __restrict__ W2, const float* __restrict__ W3,
    const float* __restrict__ W4)
{
    size_t i4 = (size_t)blockIdx.x * 256 + threadIdx.x;
    size_t n = i4 >> 8;
    int k4 = (int)(i4 & 255);
    int wsel = (int)(n >> 10);
    const float* W = (wsel == 0) ? W0 : (wsel == 1) ? W1 : (wsel == 2) ? W2
                   : (wsel == 3) ? W3 : W4;
    float4 v = ((const float4*)(W + (n & 1023) * DIMM))[k4];
    __half h[4], l[4];
    float vv[4] = {v.x, v.y, v.z, v.w};
    #pragma unroll
    for (int e = 0; e < 4; e++) {
        h[e] = __float2half_rn(vv[e]);
        l[e] = __float2half_rn(vv[e] - __half2float(h[e]));
    }
    __half* dst = g_w2 + n * K2 + k4 * 4;
    *(uint2*)(dst) = *(uint2*)h;
    if (wsel == 4) {
        *(uint2*)(dst + 1024) = *(uint2*)h;
        *(uint2*)(dst + 2048) = *(uint2*)l;
    }
}

// ---------------- kernel 1: mma.sync fp16 projection GEMM ----------------
#define BK     32
#define LDS_ROW 80
#define ATILE_B (128*LDS_ROW)
#define STG_B   (2*ATILE_B)
#define PROJ_SMEM (3*STG_B)

__global__ __launch_bounds__(256, 1) void proj_mma_kernel(
    const float* __restrict__ bq, const float* __restrict__ bk,
    const float* __restrict__ bv, const float* __restrict__ bb,
    const float* __restrict__ ba, float* __restrict__ alpha_out)
{
    extern __shared__ char dsm[];
    __shared__ float bias_s[128];
    const uint32_t sbase = s2u(dsm);
    const int tid = threadIdx.x;
    const int wid = tid >> 5, lane = tid & 31;
    const int nb = blockIdx.x, mb = blockIdx.y;
    const int wi = nb >> 3;
    const int nkit = (wi == 4) ? (K2 / BK) : (DIMM / BK);
    const int m0 = mb * 128;
    const int r0g = nb * 128;
    const int r0  = (nb & 7) * 128;

    const float* bias = (wi == 0) ? bq : (wi == 1) ? bk : (wi == 2) ? bv
                       : (wi == 3) ? bb : ba;
    if (tid < 128) bias_s[tid] = bias[r0 + tid];

    int ch0 = tid * 2;
    int arow0 = ch0 >> 2,        ac0 = (ch0 & 3);
    int arow1 = (ch0+1) >> 2,    ac1 = ((ch0+1) & 3);
    const char* aG0 = (const char*)(g_x2 + (size_t)(m0 + arow0) * K2) + ac0 * 16;
    const char* aG1 = (const char*)(g_x2 + (size_t)(m0 + arow1) * K2) + ac1 * 16;
    const char* bG0 = (const char*)(g_w2 + (size_t)(r0g + arow0) * K2) + ac0 * 16;
    const char* bG1 = (const char*)(g_w2 + (size_t)(r0g + arow1) * K2) + ac1 * 16;
    uint32_t aD0 = arow0 * LDS_ROW + ac0 * 16;
    uint32_t aD1 = arow1 * LDS_ROW + ac1 * 16;

    #define LOAD_STAGE(s, kit) do {                                     \
        uint32_t st = sbase + (s) * STG_B;                              \
        size_t kb = (size_t)(kit) * (BK * 2);                           \
        CP16(st + aD0,           aG0 + kb);                             \
        CP16(st + aD1,           aG1 + kb);                             \
        CP16(st + ATILE_B + aD0, bG0 + kb);                             \
        CP16(st + ATILE_B + aD1, bG1 + kb);                             \
    } while (0)

    const int warp_m = wid >> 2;
    const int warp_n = wid & 3;
    const int lr = lane & 15, lh = lane >> 4;
    const uint32_t aOff = (uint32_t)(warp_m * 64 + lr) * LDS_ROW + lh * 16;
    const uint32_t bOff = (uint32_t)(warp_n * 32 + lr) * LDS_ROW + lh * 16 + ATILE_B;

    float acc[4][4][4];
    #pragma unroll
    for (int i = 0; i < 4; i++)
        #pragma unroll
        for (int j = 0; j < 4; j++)
            #pragma unroll
            for (int e = 0; e < 4; e++) acc[i][j][e] = 0.0f;

    LOAD_STAGE(0, 0); CP_COMMIT();
    LOAD_STAGE(1, 1); CP_COMMIT();
    __syncthreads();

    #pragma unroll 1
    for (int i = 0; i < nkit; i++) {
        CP_WAIT1();
        __syncthreads();
        if (i + 2 < nkit) LOAD_STAGE((i + 2) % 3, i + 2);
        CP_COMMIT();

        const uint32_t st = sbase + (i % 3) * STG_B;
        #pragma unroll
        for (int ks = 0; ks < 2; ks++) {
            uint32_t af[4][4];
            #pragma unroll
            for (int mf = 0; mf < 4; mf++)
                LDM_X4(af[mf][0], af[mf][1], af[mf][2], af[mf][3],
                       st + aOff + mf * (16 * LDS_ROW) + ks * 32);
            uint32_t bf[2][4];
            #pragma unroll
            for (int nf = 0; nf < 2; nf++)
                LDM_X4(bf[nf][0], bf[nf][1], bf[nf][2], bf[nf][3],
                       st + bOff + nf * (16 * LDS_ROW) + ks * 32);
            #pragma unroll
            for (int mf = 0; mf < 4; mf++) {
                #pragma unroll
                for (int nf = 0; nf < 2; nf++) {
                    MMA16816(acc[mf][nf*2][0], acc[mf][nf*2][1],
                             acc[mf][nf*2][2], acc[mf][nf*2][3],
                             af[mf][0], af[mf][1], af[mf][2], af[mf][3],
                             bf[nf][0], bf[nf][2]);
                    MMA16816(acc[mf][nf*2+1][0], acc[mf][nf*2+1][1],
                             acc[mf][nf*2+1][2], acc[mf][nf*2+1][3],
                             af[mf][0], af[mf][1], af[mf][2], af[mf][3],
                             bf[nf][1], bf[nf][3]);
                }
            }
        }
    }

    const int g = lane >> 2, t4 = lane & 3;
    const int mBase = m0 + warp_m * 64;
    #pragma unroll
    for (int mf = 0; mf < 4; mf++) {
        #pragma unroll
        for (int nf = 0; nf < 4; nf++) {
            int nl = warp_n * 32 + nf * 8 + t4 * 2;
            float b0 = bias_s[nl], b1 = bias_s[nl + 1];
            #pragma unroll
            for (int half = 0; half < 2; half++) {
                int m = mBase + mf * 16 + g + half * 8;
                float v0 = acc[mf][nf][half*2 + 0] + b0;
                float v1 = acc[mf][nf][half*2 + 1] + b1;
                size_t off = (size_t)m * DIMM + r0 + nl;
                if (wi == 0) {
                    float s0 = v0 * 0.125f, s1 = v1 * 0.125f;
                    *(float2*)(g_q + off) = make_float2(s0, s1);
                    *(uint32_t*)(g_qh + off) = f22h(s0, s1);
                } else if (wi == 1) {
                    *(uint32_t*)(g_kh + off) = f22h(v0 * 0.125f, v1 * 0.125f);
                } else if (wi == 2) {
                    *(uint32_t*)(g_vh + off) = f22h(v0, v1);
                } else if (wi == 3) {
                    float s0 = softplusf(v0), s1 = softplusf(v1);
                    *(float2*)(g_bt + off) = make_float2(s0, s1);
                    *(uint32_t*)(g_bh + off) = f22h(s0, s1);
                } else {
                    float z0 = fminf(10.0f, fmaxf(-10.0f, v0));
                    float z1 = fminf(10.0f, fmaxf(-10.0f, v1));
                    *(float2*)(alpha_out + off) =
                        make_float2(1.0f/(1.0f+expf(-z0)), 1.0f/(1.0f+expf(-z1)));
                    *(float2*)(g_la + off) =
                        make_float2(-softplusf(-z0), -softplusf(-z1));
                }
            }
        }
    }
}

// ---------------- kernel 2: per-chunk stats ----------------
__global__ __launch_bounds__(128) void stats_kernel()
{
    const int bid = blockIdx.x;
    const int c = threadIdx.x;
    const int h = bid & 15;
    const int n = (bid >> 4) & 31;
    const int b = bid >> 9;
    const int t = b * TLEN + n * CC + c;
    const int base = t * DIMM + h * HD;
    float sla = 0.0f, sb = 0.0f;
    #pragma unroll
    for (int d4 = 0; d4 < HD; d4 += 4) {
        float4 u = *(const float4*)(g_la + base + d4);
        float4 w = *(const float4*)(g_bt + base + d4);
        sla += u.x + u.y + u.z + u.w;
        sb  += w.x + w.y + w.z + w.w;
    }
    g_bm[bid * CC + c] = sb * (1.0f/64.0f);
    __shared__ float smem[CC];
    smem[c] = sla * (1.0f/64.0f);
    __syncthreads();
    #pragma unroll
    for (int off = 1; off < CC; off <<= 1) {
        float prev = (c >= off) ? smem[c - off] : 0.0f;
        __syncthreads();
        smem[c] += prev;
        __syncthreads();
    }
    g_m[bid * CC + c] = smem[c];
}

// ---------------- kernel 3: intra-chunk attention + delta (fp16 mma) ----------------
// smem: qs[128][72]h, ks[128][72]h, vbT[64][136]h, vbmT[64][136]h, ms[128]f
#define I_QS   0
#define I_KS   (128*72)
#define I_VBT  (2*128*72)
#define I_VBMT (2*128*72 + 64*136)
#define I_HALVES (2*128*72 + 2*64*136)
#define I_BYTES (I_HALVES*2 + 128*4)     /* 72192 */

__global__ __launch_bounds__(256, 1) void intra_kernel(float* __restrict__ y_out)
{
    extern __shared__ __half smh[];
    __half* qs   = smh + I_QS;
    __half* ks   = smh + I_KS;
    __half* vbT  = smh + I_VBT;
    __half* vbmT = smh + I_VBMT;
    float*  ms   = (float*)(smh + I_HALVES);
    const uint32_t qsU = s2u(qs), ksU = s2u(ks);
    const uint32_t vbTU = s2u(vbT), vbmTU = s2u(vbmT);

    const int tid = threadIdx.x;
    const int bid = blockIdx.x;
    const int h = bid & 15;
    const int n = (bid >> 4) & 31;
    const int b = bid >> 9;
    const int tbase = b * TLEN + n * CC;

    // ---- load phase ----
    #pragma unroll
    for (int it = 0; it < 8; it++) {
        int f  = tid + it * 256;          // 0..2047
        int c  = f >> 4;                  // 0..127
        int d4 = (f & 15) << 2;           // 0..60
        size_t gi = (size_t)(tbase + c) * DIMM + h * HD + d4;
        *(uint2*)(qs + c*72 + d4) = *(const uint2*)(g_qh + gi);
        *(uint2*)(ks + c*72 + d4) = *(const uint2*)(g_kh + gi);
        uint2 vv = *(const uint2*)(g_vh + gi);
        uint2 bv = *(const uint2*)(g_bh + gi);
        const __half* vh = (const __half*)&vv;
        const __half* bh = (const __half*)&bv;
        float bm = g_bm[bid * CC + c];
        #pragma unroll
        for (int e = 0; e < 4; e++) {
            float vf = __half2float(vh[e]);
            vbT [(d4+e)*136 + c] = __float2half_rn(vf * __half2float(bh[e]));
            vbmT[(d4+e)*136 + c] = __float2half_rn(vf * bm);
        }
    }
    if (tid < 128) ms[tid] = g_m[bid * CC + tid];
    __syncthreads();

    const int w = tid >> 5, lane = tid & 31;
    const int g = lane >> 2, t4 = lane & 3;
    const int lr = lane & 15, lh = lane >> 4;
    const int i0 = w * 16;

    // ---- S = Q K^T  (rows i0..i0+15, tiles j<=2w+1) ----
    float sacc[16][4];
    #pragma unroll
    for (int j = 0; j < 16; j++)
        #pragma unroll
        for (int e = 0; e < 4; e++) sacc[j][e] = 0.0f;

    #pragma unroll
    for (int ka = 0; ka < 4; ka++) {
        uint32_t a0,a1,a2,a3;
        LDM_X4(a0,a1,a2,a3, qsU + (uint32_t)(i0 + lr)*144 + lh*16 + ka*32);
        #pragma unroll
        for (int jp = 0; jp < 8; jp++) {
            if (jp <= w) {
                uint32_t b0,b1,b2,b3;
                LDM_X4(b0,b1,b2,b3, ksU + (uint32_t)(jp*16 + lr)*144 + lh*16 + ka*32);
                MMA16816(sacc[2*jp][0], sacc[2*jp][1], sacc[2*jp][2], sacc[2*jp][3],
                         a0,a1,a2,a3, b0,b2);
                MMA16816(sacc[2*jp+1][0], sacc[2*jp+1][1], sacc[2*jp+1][2], sacc[2*jp+1][3],
                         a0,a1,a2,a3, b1,b3);
            }
        }
    }

    // ---- decay * mask ----
    {
        float mi0 = ms[i0 + g], mi1 = ms[i0 + g + 8];
        int r0 = i0 + g, r1 = i0 + g + 8;
        #pragma unroll
        for (int j = 0; j < 16; j++) {
            if (j <= 2*w + 1) {
                int c0 = j*8 + t4*2, c1 = c0 + 1;
                float mj0 = ms[c0], mj1 = ms[c1];
                sacc[j][0] = (c0 <= r0) ? sacc[j][0] * expf(mi0 - mj0) : 0.0f;
                sacc[j][1] = (c1 <= r0) ? sacc[j][1] * expf(mi0 - mj1) : 0.0f;
                sacc[j][2] = (c0 <= r1) ? sacc[j][2] * expf(mi1 - mj0) : 0.0f;
                sacc[j][3] = (c1 <= r1) ? sacc[j][3] * expf(mi1 - mj1) : 0.0f;
            }
        }
    }

    // ---- convert S fragments -> fp16 A fragments ----
    uint32_t ha[8][4];
    #pragma unroll
    for (int k2 = 0; k2 < 8; k2++) {
        if (k2 <= w) {
            ha[k2][0] = f22h(sacc[2*k2][0],   sacc[2*k2][1]);
            ha[k2][1] = f22h(sacc[2*k2][2],   sacc[2*k2][3]);
            ha[k2][2] = f22h(sacc[2*k2+1][0], sacc[2*k2+1][1]);
            ha[k2][3] = f22h(sacc[2*k2+1][2], sacc[2*k2+1][3]);
        }
    }

    // ---- Y = S @ VB ----
    float ya[8][4];
    #pragma unroll
    for (int j = 0; j < 8; j++)
        #pragma unroll
        for (int e = 0; e < 4; e++) ya[j][e] = 0.0f;

    #pragma unroll
    for (int k2 = 0; k2 < 8; k2++) {
        if (k2 <= w) {
            #pragma unroll
            for (int np = 0; np < 4; np++) {
                uint32_t b0,b1,b2,b3;
                LDM_X4(b0,b1,b2,b3, vbTU + (uint32_t)(np*16 + lr)*272 + lh*16 + k2*32);
                MMA16816(ya[2*np][0], ya[2*np][1], ya[2*np][2], ya[2*np][3],
                         ha[k2][0], ha[k2][1], ha[k2][2], ha[k2][3], b0, b2);
                MMA16816(ya[2*np+1][0], ya[2*np+1][1], ya[2*np+1][2], ya[2*np+1][3],
                         ha[k2][0], ha[k2][1], ha[k2][2], ha[k2][3], b1, b3);
            }
        }
    }
    #pragma unroll
    for (int nt = 0; nt < 8; nt++) {
        int dd = nt*8 + t4*2;
        size_t o0 = (size_t)(tbase + i0 + g) * DIMM + h * HD + dd;
        *(float2*)(y_out + o0)            = make_float2(ya[nt][0], ya[nt][1]);
        *(float2*)(y_out + o0 + 8*DIMM)   = make_float2(ya[nt][2], ya[nt][3]);
    }

    // ---- delta = K^T @ VBm  (64x64, k=128) ----
    {
        const int mt = w >> 1;          // 0..3 feature-tile
        const int nh = w & 1;           // 0..1 dd-half
        float da[4][4];
        #pragma unroll
        for (int j = 0; j < 4; j++)
            #pragma unroll
            for (int e = 0; e < 4; e++) da[j][e] = 0.0f;

        const int lg = lane >> 3, li = lane & 7;
        const int rowc_off = li + ((lg >> 1) & 1) * 8;
        const int colf = mt*16 + (lg & 1) * 8;
        #pragma unroll
        for (int ka = 0; ka < 8; ka++) {
            uint32_t a0,a1,a2,a3;
            LDM_X4T(a0,a1,a2,a3,
                    ksU + (uint32_t)(ka*16 + rowc_off)*144 + colf*2);
            #pragma unroll
            for (int np = 0; np < 2; np++) {
                uint32_t b0,b1,b2,b3;
                LDM_X4(b0,b1,b2,b3,
                       vbmTU + (uint32_t)(nh*32 + np*16 + lr)*272 + lh*16 + ka*32);
                MMA16816(da[2*np][0], da[2*np][1], da[2*np][2], da[2*np][3],
                         a0,a1,a2,a3, b0,b2);
                MMA16816(da[2*np+1][0], da[2*np+1][1], da[2*np+1][2], da[2*np+1][3],
                         a0,a1,a2,a3, b1,b3);
            }
        }
        size_t dbase = (size_t)bid * 4096;
        #pragma unroll
        for (int nt = 0; nt < 4; nt++) {
            int dd = nh*32 + nt*8 + t4*2;
            int kk = mt*16 + g;
            *(float2*)(g_delta + dbase + (size_t)kk*64 + dd)
                = make_float2(da[nt][0], da[nt][1]);
            *(float2*)(g_delta + dbase + (size_t)(kk+8)*64 + dd)
                = make_float2(da[nt][2], da[nt][3]);
        }
    }
}

// ---------------- kernel 4: state recurrence ----------------
__global__ __launch_bounds__(256) void recur_kernel(float* __restrict__ state_out)
{
    const int bh = blockIdx.x;
    const int b = bh >> 4, h = bh & 15;
    const int tid = threadIdx.x;
    float s[16];
    #pragma unroll
    for (int e = 0; e < 16; e++) s[e] = 0.0f;
    #pragma unroll 1
    for (int n = 0; n < NCH; n++) {
        const int cbid = (b * NCH + n) * HEADS + h;
        float asum = expf(g_m[cbid * CC + (CC - 1)]);
        size_t base = (size_t)cbid * 4096;
        #pragma unroll
        for (int e = 0; e < 16; e++) {
            int idx = tid + e * 256;
            g_stin[base + idx] = s[e];
            s[e] = s[e] * asum + g_delta[base + idx];
        }
    }
    size_t ob = (size_t)bh * 4096;
    #pragma unroll
    for (int e = 0; e < 16; e++) state_out[ob + tid + e * 256] = s[e];
}

// ---------------- kernel 5: y += (q @ state_in) * curve ----------------
__global__ __launch_bounds__(256) void ymem_kernel(float* __restrict__ y_out)
{
    __shared__ float qs[128*68];
    __shared__ float ss[64*68];
    __shared__ float cv[128];
    const int tid = threadIdx.x;
    const int bid = blockIdx.x;
    const int h = bid & 15;
    const int n = (bid >> 4) & 31;
    const int b = bid >> 9;
    const int tb = b * TLEN + n * CC;
    size_t sbase = (size_t)bid * 4096;

    #pragma unroll
    for (int it = 0; it < 8; it++) {
        int f = tid + it * 256;
        int c = f >> 4, d4 = (f & 15) << 2;
        *(float4*)(qs + c*68 + d4) =
            *(const float4*)(g_q + (tb + c) * DIMM + h * HD + d4);
    }
    #pragma unroll
    for (int it = 0; it < 4; it++) {
        int f = tid + it * 256;
        int kk = f >> 4, d4 = (f & 15) << 2;
        *(float4*)(ss + kk*68 + d4) = *(const float4*)(g_stin + sbase + kk*64 + d4);
    }
    if (tid < 128) cv[tid] = expf(g_m[bid * CC + tid]);
    __syncthreads();

    const int tx = tid & 7, ty = tid >> 3;
    const int c0 = ty * 4, dd0 = tx * 8;
    float a0[8], a1[8], a2[8], a3[8];
    #pragma unroll
    for (int e = 0; e < 8; e++) { a0[e]=0.f; a1[e]=0.f; a2[e]=0.f; a3[e]=0.f; }
    #pragma unroll 4
    for (int kk = 0; kk < 64; kk++) {
        float q0 = qs[(c0+0)*68 + kk];
        float q1 = qs[(c0+1)*68 + kk];
        float q2 = qs[(c0+2)*68 + kk];
        float q3 = qs[(c0+3)*68 + kk];
        float sv[8];
        *(float4*)&sv[0] = *(const float4*)&ss[kk*68 + dd0];
        *(float4*)&sv[4] = *(const float4*)&ss[kk*68 + dd0 + 4];
        #pragma unroll
        for (int e = 0; e < 8; e++) {
            a0[e] = fmaf(q0, sv[e], a0[e]);
            a1[e] = fmaf(q1, sv[e], a1[e]);
            a2[e] = fmaf(q2, sv[e], a2[e]);
            a3[e] = fmaf(q3, sv[e], a3[e]);
        }
    }
    #pragma unroll
    for (int i = 0; i < 4; i++) {
        float* ap = (i==0)?a0:(i==1)?a1:(i==2)?a2:a3;
        float cc = cv[c0 + i];
        size_t off = (size_t)(tb + c0 + i) * DIMM + h * HD + dd0;
        float4 o0 = *(float4*)(y_out + off);
        float4 o1 = *(float4*)(y_out + off + 4);
        o0.x += ap[0]*cc; o0.y += ap[1]*cc; o0.z += ap[2]*cc; o0.w += ap[3]*cc;
        o1.x += ap[4]*cc; o1.y += ap[5]*cc; o1.z += ap[6]*cc; o1.w += ap[7]*cc;
        *(float4*)(y_out + off)     = o0;
        *(float4*)(y_out + off + 4) = o1;
    }
}

// ---------------- launch ----------------
extern "C" void kernel_launch(void* const* d_in, const int* in_sizes, int n_in,
                              void* d_out, int out_size)
{
    (void)in_sizes; (void)n_in; (void)out_size;
    const float* x  = (const float*)d_in[0];
    const float* Wq = (const float*)d_in[1];
    const float* bq = (const float*)d_in[2];
    const float* Wk = (const float*)d_in[3];
    const float* bk = (const float*)d_in[4];
    const float* Wv = (const float*)d_in[5];
    const float* bv = (const float*)d_in[6];
    const float* Wb = (const float*)d_in[7];
    const float* bb = (const float*)d_in[8];
    const float* Wa = (const float*)d_in[9];
    const float* ba = (const float*)d_in[10];

    float* out       = (float*)d_out;
    float* y_out     = out;
    float* state_out = out + YN;
    float* alpha_out = out + YN + SN;

    cudaFuncSetAttribute(intra_kernel,
                         cudaFuncAttributeMaxDynamicSharedMemorySize, I_BYTES);
    cudaFuncSetAttribute(proj_mma_kernel,
                         cudaFuncAttributeMaxDynamicSharedMemorySize, PROJ_SMEM);

    conv_x_kernel<<<MTOT * DIMM / 4 / 256, 256>>>(x);
    conv_w_kernel<<<NOUT * DIMM / 4 / 256, 256>>>(Wq, Wk, Wv, Wb, Wa);
    dim3 g1(40, 128);
    proj_mma_kernel<<<g1, 256, PROJ_SMEM>>>(bq, bk, bv, bb, ba, alpha_out);
    stats_kernel<<<BSZ*NCH*HEADS, 128>>>();
    intra_kernel<<<BSZ*NCH*HEADS, 256, I_BYTES>>>(y_out);
    recur_kernel<<<BSZ*HEADS, 256>>>(state_out);
    ymem_kernel<<<BSZ*NCH*HEADS, 256>>>(y_out);
}